// round 8
// baseline (speedup 1.0000x reference)
#include <cuda_runtime.h>
#include <cstdint>
#include <cstddef>

// EdgeEncoder:
//   K1 (proj, R6 shape): P = tf32(node_emb)@tf32(W1a)+b1 ; Q = tf32(node_emb)@tf32(W1b)
//   K2 (edge v2): persistent, cp.async double-buffered gather, W2 B-frags in regs,
//                 H = relu(P[u]+Q[v]+sel*w1c); out = relu(tf32(H)@tf32(W2)+b2), staged STG.
// edge_index is int32.

#define LDX 132
#define LDW 136

#define MAXROWS 401408
__device__ float P_buf[(size_t)MAXROWS * 128];
__device__ float Q_buf[(size_t)MAXROWS * 128];

__device__ __forceinline__ float f2tf(float f) {
    uint32_t r;
    asm("cvt.rna.tf32.f32 %0, %1;" : "=r"(r) : "f"(f));
    return __uint_as_float(r);
}
__device__ __forceinline__ uint32_t f2tf_u(float f) {
    uint32_t r;
    asm("cvt.rna.tf32.f32 %0, %1;" : "=r"(r) : "f"(f));
    return r;
}
__device__ __forceinline__ uint32_t smem_u32(const void* p) {
    uint32_t a;
    asm("{ .reg .u64 t; cvta.to.shared.u64 t, %1; cvt.u32.u64 %0, t; }" : "=r"(a) : "l"(p));
    return a;
}
__device__ __forceinline__ void cp16(uint32_t dst, const void* src) {
    asm volatile("cp.async.cg.shared.global [%0], [%1], 16;" :: "r"(dst), "l"(src));
}
#define CP_COMMIT() asm volatile("cp.async.commit_group;" ::: "memory")
#define CP_WAIT1()  asm volatile("cp.async.wait_group 1;" ::: "memory")
#define CP_WAIT0()  asm volatile("cp.async.wait_group 0;" ::: "memory")

__device__ __forceinline__ void mma8(float c[4], const uint32_t a[4], uint32_t b0, uint32_t b1) {
    asm("mma.sync.aligned.m16n8k8.row.col.f32.tf32.tf32.f32 "
        "{%0,%1,%2,%3}, {%4,%5,%6,%7}, {%8,%9}, {%0,%1,%2,%3};"
        : "+f"(c[0]), "+f"(c[1]), "+f"(c[2]), "+f"(c[3])
        : "r"(a[0]), "r"(a[1]), "r"(a[2]), "r"(a[3]), "r"(b0), "r"(b1));
}

__device__ __forceinline__ void load_w_tile(float* __restrict__ Ws,
                                            const float* __restrict__ src_f,
                                            int tid, int nthr) {
    const float4* src = reinterpret_cast<const float4*>(src_f);
    for (int i = tid; i < 128 * 32; i += nthr) {
        const int k = i >> 5, c = i & 31;
        float4 v = src[i];
        float4 w;
        w.x = f2tf(v.x); w.y = f2tf(v.y); w.z = f2tf(v.z); w.w = f2tf(v.w);
        reinterpret_cast<float4*>(Ws + k * LDW + c * 4)[0] = w;
    }
}

// ================= Kernel 1: node projections (R6 shape: 256 thr, 256-row tiles) ==========
__global__ void __launch_bounds__(256, 1) node_proj_kernel(
    const float* __restrict__ node_emb,
    const float* __restrict__ W1,
    const float* __restrict__ b1,
    int BN)
{
    extern __shared__ float smem[];
    float* Xs  = smem;
    float* Ws  = Xs + 256 * LDX;
    float* b1s = Ws + 128 * LDW;

    const int tid  = threadIdx.x;
    const int wid  = tid >> 5;
    const int lane = tid & 31;
    const int gq   = lane >> 2;
    const int tq   = lane & 3;
    const int m_warp = (wid & 3) * 64;
    const int n_warp = (wid >> 2) * 64;
    const int gbase = blockIdx.x * 256;

    if (tid < 128) b1s[tid] = b1[tid];

    {
        int g = gbase + tid;
        if (g >= BN) g = BN - 1;
        const float4* src = reinterpret_cast<const float4*>(node_emb + (size_t)g * 128);
        float* xrow = Xs + tid * LDX;
#pragma unroll
        for (int i = 0; i < 32; ++i) {
            float4 v = src[i];
            float4 w;
            w.x = f2tf(v.x); w.y = f2tf(v.y); w.z = f2tf(v.z); w.w = f2tf(v.w);
            reinterpret_cast<float4*>(xrow + i * 4)[0] = w;
        }
    }
    load_w_tile(Ws, W1, tid, 256);
    __syncthreads();

    float acc[4][8][4];
#pragma unroll
    for (int mt = 0; mt < 4; ++mt)
#pragma unroll
        for (int nt = 0; nt < 8; ++nt)
#pragma unroll
            for (int i = 0; i < 4; ++i) acc[mt][nt][i] = 0.f;

#pragma unroll
    for (int ks = 0; ks < 16; ++ks) {
        const int k0 = ks * 8;
        uint32_t a[4][4];
#pragma unroll
        for (int mt = 0; mt < 4; ++mt) {
            const int r0 = m_warp + mt * 16 + gq;
            a[mt][0] = __float_as_uint(Xs[r0 * LDX + k0 + tq]);
            a[mt][1] = __float_as_uint(Xs[(r0 + 8) * LDX + k0 + tq]);
            a[mt][2] = __float_as_uint(Xs[r0 * LDX + k0 + tq + 4]);
            a[mt][3] = __float_as_uint(Xs[(r0 + 8) * LDX + k0 + tq + 4]);
        }
#pragma unroll
        for (int nt = 0; nt < 8; ++nt) {
            const int n0 = n_warp + nt * 8 + gq;
            const uint32_t b0 = __float_as_uint(Ws[(k0 + tq) * LDW + n0]);
            const uint32_t b1r = __float_as_uint(Ws[(k0 + tq + 4) * LDW + n0]);
#pragma unroll
            for (int mt = 0; mt < 4; ++mt) mma8(acc[mt][nt], a[mt], b0, b1r);
        }
    }

#pragma unroll
    for (int nt = 0; nt < 8; ++nt) {
        const int n0 = n_warp + nt * 8 + tq * 2;
        const float bv0 = b1s[n0], bv1 = b1s[n0 + 1];
#pragma unroll
        for (int mt = 0; mt < 4; ++mt) {
            const int r0 = gbase + m_warp + mt * 16 + gq;
            if (r0 < BN)
                *reinterpret_cast<float2*>(P_buf + (size_t)r0 * 128 + n0) =
                    make_float2(acc[mt][nt][0] + bv0, acc[mt][nt][1] + bv1);
            if (r0 + 8 < BN)
                *reinterpret_cast<float2*>(P_buf + (size_t)(r0 + 8) * 128 + n0) =
                    make_float2(acc[mt][nt][2] + bv0, acc[mt][nt][3] + bv1);
            acc[mt][nt][0] = acc[mt][nt][1] = acc[mt][nt][2] = acc[mt][nt][3] = 0.f;
        }
    }
    __syncthreads();
    load_w_tile(Ws, W1 + 128 * 128, tid, 256);
    __syncthreads();

#pragma unroll
    for (int ks = 0; ks < 16; ++ks) {
        const int k0 = ks * 8;
        uint32_t a[4][4];
#pragma unroll
        for (int mt = 0; mt < 4; ++mt) {
            const int r0 = m_warp + mt * 16 + gq;
            a[mt][0] = __float_as_uint(Xs[r0 * LDX + k0 + tq]);
            a[mt][1] = __float_as_uint(Xs[(r0 + 8) * LDX + k0 + tq]);
            a[mt][2] = __float_as_uint(Xs[r0 * LDX + k0 + tq + 4]);
            a[mt][3] = __float_as_uint(Xs[(r0 + 8) * LDX + k0 + tq + 4]);
        }
#pragma unroll
        for (int nt = 0; nt < 8; ++nt) {
            const int n0 = n_warp + nt * 8 + gq;
            const uint32_t b0 = __float_as_uint(Ws[(k0 + tq) * LDW + n0]);
            const uint32_t b1r = __float_as_uint(Ws[(k0 + tq + 4) * LDW + n0]);
#pragma unroll
            for (int mt = 0; mt < 4; ++mt) mma8(acc[mt][nt], a[mt], b0, b1r);
        }
    }
#pragma unroll
    for (int nt = 0; nt < 8; ++nt) {
        const int n0 = n_warp + nt * 8 + tq * 2;
#pragma unroll
        for (int mt = 0; mt < 4; ++mt) {
            const int r0 = gbase + m_warp + mt * 16 + gq;
            if (r0 < BN)
                *reinterpret_cast<float2*>(Q_buf + (size_t)r0 * 128 + n0) =
                    make_float2(acc[mt][nt][0], acc[mt][nt][1]);
            if (r0 + 8 < BN)
                *reinterpret_cast<float2*>(Q_buf + (size_t)(r0 + 8) * 128 + n0) =
                    make_float2(acc[mt][nt][2], acc[mt][nt][3]);
        }
    }
}

// ================= Kernel 2: edge v2 =================
// smem float offsets
#define PB(buf) ((buf) * 8448)              // 64*132 each
#define QB(buf) (16896 + (buf) * 8448)
#define XSO 33792
#define OSO 42240
#define IDXO 50688                          // int2[2][64] = 256 ints
#define SELO 50944                          // float[2][64]
#define W1CO 51072                          // float[128]
#define B2O  51200                          // float[128]
#define SMF  51328                          // total floats (205,312 B)

__global__ void __launch_bounds__(256, 1) edge_kernel(
    const int* __restrict__ edge_index,
    const float* __restrict__ edge_sel,
    const float* __restrict__ W1,
    const float* __restrict__ W2,
    const float* __restrict__ b2,
    float* __restrict__ out,
    int E, int bpb, int n_nodes, int ntiles)
{
    extern __shared__ float smem[];
    float* Xs   = smem + XSO;
    float* Os   = smem + OSO;
    int2*  idxs = reinterpret_cast<int2*>(smem + IDXO);
    float* sels = smem + SELO;
    float* w1cs = smem + W1CO;
    float* b2s  = smem + B2O;
    const uint32_t sbase = smem_u32(smem);

    const int tid  = threadIdx.x;
    const int wid  = tid >> 5;
    const int lane = tid & 31;
    const int gq   = lane >> 2;
    const int tq   = lane & 3;
    const int m_warp = (wid & 1) * 32;
    const int n_warp = (wid >> 1) * 32;

    if (tid < 128) {
        w1cs[tid] = W1[256 * 128 + tid];
        b2s[tid]  = b2[tid];
    }

    // W2 B-fragments -> 128 registers (one-time)
    uint32_t breg[16][4][2];
#pragma unroll
    for (int ks = 0; ks < 16; ++ks)
#pragma unroll
        for (int nt = 0; nt < 4; ++nt) {
            const int n0 = n_warp + nt * 8 + gq;
            breg[ks][nt][0] = f2tf_u(W2[(ks * 8 + tq) * 128 + n0]);
            breg[ks][nt][1] = f2tf_u(W2[(ks * 8 + tq + 4) * 128 + n0]);
        }

    const int stride = gridDim.x;
    const int t0 = blockIdx.x;
    auto ebase = [&](int t) -> long long {
        const int b = t / bpb;
        return (long long)b * E + (long long)(t - b * bpb) * 64;
    };

    int2  idx_n;
    float sel_n;
    // prologue: idx(t0) -> smem buf 0 ; idx(t1) -> regs
    {
        const long long eb0 = ebase(t0);
        if (tid < 64) {
            idxs[tid] = reinterpret_cast<const int2*>(edge_index)[eb0 + tid];
            sels[tid] = edge_sel[eb0 + tid];
        }
        int t1 = t0 + stride; if (t1 >= ntiles) t1 = t0;
        const long long eb1 = ebase(t1);
        if (tid < 64) {
            idx_n = reinterpret_cast<const int2*>(edge_index)[eb1 + tid];
            sel_n = edge_sel[eb1 + tid];
        }
    }
    __syncthreads();

    // gather(t0) into buf 0
    {
        const size_t rowbase = (size_t)(t0 / bpb) * n_nodes;
#pragma unroll
        for (int j = 0; j < 16; ++j) {
            const int rm  = j * 8 + wid;
            const int row = rm >> 1;
            const int isQ = rm & 1;
            const int2 e = idxs[row];
            int nd = isQ ? e.y : e.x;
            nd = min(max(nd, 0), n_nodes - 1);
            const float* src = (isQ ? Q_buf : P_buf) + (rowbase + nd) * 128 + lane * 4;
            const uint32_t dst = sbase + (uint32_t)(((isQ ? QB(0) : PB(0)) + row * LDX + lane * 4) * 4);
            cp16(dst, src);
        }
        CP_COMMIT();
    }

    int i = 0;
    for (int t = t0; t < ntiles; t += stride, ++i) {
        const int cur = i & 1, nxt = cur ^ 1;
        const long long eb = ebase(t);
        int t1 = t + stride; if (t1 >= ntiles) t1 = t;

        // stage idx(t+1) to smem, prefetch idx(t+2)
        if (tid < 64) {
            idxs[nxt * 64 + tid] = idx_n;
            sels[nxt * 64 + tid] = sel_n;
            int t2 = t + 2 * stride; if (t2 >= ntiles) t2 = t;
            const long long eb2 = ebase(t2);
            idx_n = reinterpret_cast<const int2*>(edge_index)[eb2 + tid];
            sel_n = edge_sel[eb2 + tid];
        }
        __syncthreads();

        // issue gather(t+1) into buf nxt
        {
            const size_t rowbase = (size_t)(t1 / bpb) * n_nodes;
#pragma unroll
            for (int j = 0; j < 16; ++j) {
                const int rm  = j * 8 + wid;
                const int row = rm >> 1;
                const int isQ = rm & 1;
                const int2 e = idxs[nxt * 64 + row];
                int nd = isQ ? e.y : e.x;
                nd = min(max(nd, 0), n_nodes - 1);
                const float* src = (isQ ? Q_buf : P_buf) + (rowbase + nd) * 128 + lane * 4;
                const uint32_t dst = sbase + (uint32_t)(((isQ ? QB(nxt) : PB(nxt)) + row * LDX + lane * 4) * 4);
                cp16(dst, src);
            }
            CP_COMMIT();
        }

        CP_WAIT1();          // gather(t) complete
        __syncthreads();

        // combine: H = relu(P+Q+sel*w1c) -> Xs (tf32)
        {
            const int e_loc = tid >> 2, q = tid & 3;
            const float s = sels[cur * 64 + e_loc];
            const float* Pr = smem + PB(cur) + e_loc * LDX + q * 32;
            const float* Qr = smem + QB(cur) + e_loc * LDX + q * 32;
            float* xrow = Xs + e_loc * LDX + q * 32;
            const float4* w4 = reinterpret_cast<const float4*>(w1cs + q * 32);
#pragma unroll
            for (int ii = 0; ii < 8; ++ii) {
                const int c4 = (ii + 2 * q) & 7;
                const float4 a = reinterpret_cast<const float4*>(Pr)[c4];
                const float4 b = reinterpret_cast<const float4*>(Qr)[c4];
                const float4 w = w4[c4];
                float4 r;
                r.x = f2tf(fmaxf(a.x + b.x + s * w.x, 0.f));
                r.y = f2tf(fmaxf(a.y + b.y + s * w.y, 0.f));
                r.z = f2tf(fmaxf(a.z + b.z + s * w.z, 0.f));
                r.w = f2tf(fmaxf(a.w + b.w + s * w.w, 0.f));
                reinterpret_cast<float4*>(xrow)[c4] = r;
            }
        }
        __syncthreads();

        // GEMM: A from Xs, B from regs
        float acc[2][4][4];
#pragma unroll
        for (int mt = 0; mt < 2; ++mt)
#pragma unroll
            for (int nt = 0; nt < 4; ++nt)
#pragma unroll
                for (int k = 0; k < 4; ++k) acc[mt][nt][k] = 0.f;

#pragma unroll
        for (int ks = 0; ks < 16; ++ks) {
            const int k0 = ks * 8;
            uint32_t a[2][4];
#pragma unroll
            for (int mt = 0; mt < 2; ++mt) {
                const int r0 = m_warp + mt * 16 + gq;
                a[mt][0] = __float_as_uint(Xs[r0 * LDX + k0 + tq]);
                a[mt][1] = __float_as_uint(Xs[(r0 + 8) * LDX + k0 + tq]);
                a[mt][2] = __float_as_uint(Xs[r0 * LDX + k0 + tq + 4]);
                a[mt][3] = __float_as_uint(Xs[(r0 + 8) * LDX + k0 + tq + 4]);
            }
#pragma unroll
            for (int nt = 0; nt < 4; ++nt) {
                mma8(acc[0][nt], a[0], breg[ks][nt][0], breg[ks][nt][1]);
                mma8(acc[1][nt], a[1], breg[ks][nt][0], breg[ks][nt][1]);
            }
        }

        // epilogue: relu(acc+b2) -> Os, then coalesced STG
#pragma unroll
        for (int nt = 0; nt < 4; ++nt) {
            const int n0 = n_warp + nt * 8 + tq * 2;
            const float bv0 = b2s[n0], bv1 = b2s[n0 + 1];
#pragma unroll
            for (int mt = 0; mt < 2; ++mt) {
                const int r0 = m_warp + mt * 16 + gq;
                *reinterpret_cast<float2*>(Os + r0 * LDX + n0) =
                    make_float2(fmaxf(acc[mt][nt][0] + bv0, 0.f),
                                fmaxf(acc[mt][nt][1] + bv1, 0.f));
                *reinterpret_cast<float2*>(Os + (r0 + 8) * LDX + n0) =
                    make_float2(fmaxf(acc[mt][nt][2] + bv0, 0.f),
                                fmaxf(acc[mt][nt][3] + bv1, 0.f));
            }
        }
        __syncthreads();
#pragma unroll
        for (int j = 0; j < 8; ++j) {
            const int row = j * 8 + wid;
            const float4 v = reinterpret_cast<const float4*>(Os + row * LDX)[lane];
            reinterpret_cast<float4*>(out + (size_t)(eb + row) * 128)[lane] = v;
        }
    }
    CP_WAIT0();
}

extern "C" void kernel_launch(void* const* d_in, const int* in_sizes, int n_in,
                              void* d_out, int out_size) {
    const float* node_emb   = (const float*)d_in[0];
    const int*   edge_index = (const int*)d_in[1];   // int32
    const float* edge_sel   = (const float*)d_in[2];
    const float* W1         = (const float*)d_in[3];
    const float* b1         = (const float*)d_in[4];
    const float* W2         = (const float*)d_in[5];
    const float* b2         = (const float*)d_in[6];
    float*       out        = (float*)d_out;

    const int B  = 4;
    const int E  = in_sizes[2] / B;
    const int n_nodes = in_sizes[0] / (B * 128);
    const int BN = B * n_nodes;

    const int grid1 = (BN + 255) / 256;
    const int bpb   = E / 64;
    const int ntiles = B * bpb;

    int dev = 0, sms = 148;
    cudaGetDevice(&dev);
    cudaDeviceGetAttribute(&sms, cudaDevAttrMultiProcessorCount, dev);
    const int grid2 = sms < ntiles ? sms : ntiles;

    const size_t smem1 = (size_t)(256 * LDX + 128 * LDW + 128) * sizeof(float);
    const size_t smem2 = (size_t)SMF * sizeof(float);
    cudaFuncSetAttribute(node_proj_kernel,
                         cudaFuncAttributeMaxDynamicSharedMemorySize, (int)smem1);
    cudaFuncSetAttribute(edge_kernel,
                         cudaFuncAttributeMaxDynamicSharedMemorySize, (int)smem2);

    node_proj_kernel<<<grid1, 256, smem1>>>(node_emb, W1, b1, BN);
    edge_kernel<<<grid2, 256, smem2>>>(edge_index, edge_sel, W1, W2, b2, out,
                                       E, bpb, n_nodes, ntiles);
}

// round 9
// speedup vs baseline: 1.4624x; 1.4624x over previous
#include <cuda_runtime.h>
#include <cstdint>
#include <cstddef>

// EdgeEncoder:
//   K1 (proj): P = tf32(node_emb)@tf32(W1a)+b1 ; Q = tf32(node_emb)@tf32(W1b)
//   K2 (edge v3): 2 CTAs/SM. P gathered to regs (__ldcg), Q via cp.async to smem,
//                 combine in-place (H over Q), GEMM2 A=H(smem) B=W2(smem), staged STG (.cs).
// edge_index is int32.

#define LDX 132
#define LDW 136

#define MAXROWS 401408
__device__ float P_buf[(size_t)MAXROWS * 128];
__device__ float Q_buf[(size_t)MAXROWS * 128];

__device__ __forceinline__ float f2tf(float f) {
    uint32_t r;
    asm("cvt.rna.tf32.f32 %0, %1;" : "=r"(r) : "f"(f));
    return __uint_as_float(r);
}
__device__ __forceinline__ uint32_t smem_u32(const void* p) {
    uint32_t a;
    asm("{ .reg .u64 t; cvta.to.shared.u64 t, %1; cvt.u32.u64 %0, t; }" : "=r"(a) : "l"(p));
    return a;
}
__device__ __forceinline__ void cp16(uint32_t dst, const void* src) {
    asm volatile("cp.async.cg.shared.global [%0], [%1], 16;" :: "r"(dst), "l"(src));
}
#define CP_COMMIT() asm volatile("cp.async.commit_group;" ::: "memory")
#define CP_WAIT0()  asm volatile("cp.async.wait_group 0;" ::: "memory")

__device__ __forceinline__ void mma8(float c[4], const uint32_t a[4], uint32_t b0, uint32_t b1) {
    asm("mma.sync.aligned.m16n8k8.row.col.f32.tf32.tf32.f32 "
        "{%0,%1,%2,%3}, {%4,%5,%6,%7}, {%8,%9}, {%0,%1,%2,%3};"
        : "+f"(c[0]), "+f"(c[1]), "+f"(c[2]), "+f"(c[3])
        : "r"(a[0]), "r"(a[1]), "r"(a[2]), "r"(a[3]), "r"(b0), "r"(b1));
}

__device__ __forceinline__ void load_w_tile(float* __restrict__ Ws,
                                            const float* __restrict__ src_f,
                                            int tid, int nthr) {
    const float4* src = reinterpret_cast<const float4*>(src_f);
    for (int i = tid; i < 128 * 32; i += nthr) {
        const int k = i >> 5, c = i & 31;
        float4 v = src[i];
        float4 w;
        w.x = f2tf(v.x); w.y = f2tf(v.y); w.z = f2tf(v.z); w.w = f2tf(v.w);
        reinterpret_cast<float4*>(Ws + k * LDW + c * 4)[0] = w;
    }
}

// ================= Kernel 1: node projections (unchanged, 256 thr, 256-row tiles) ==========
__global__ void __launch_bounds__(256, 1) node_proj_kernel(
    const float* __restrict__ node_emb,
    const float* __restrict__ W1,
    const float* __restrict__ b1,
    int BN)
{
    extern __shared__ float smem[];
    float* Xs  = smem;
    float* Ws  = Xs + 256 * LDX;
    float* b1s = Ws + 128 * LDW;

    const int tid  = threadIdx.x;
    const int wid  = tid >> 5;
    const int lane = tid & 31;
    const int gq   = lane >> 2;
    const int tq   = lane & 3;
    const int m_warp = (wid & 3) * 64;
    const int n_warp = (wid >> 2) * 64;
    const int gbase = blockIdx.x * 256;

    if (tid < 128) b1s[tid] = b1[tid];

    {
        int g = gbase + tid;
        if (g >= BN) g = BN - 1;
        const float4* src = reinterpret_cast<const float4*>(node_emb + (size_t)g * 128);
        float* xrow = Xs + tid * LDX;
#pragma unroll
        for (int i = 0; i < 32; ++i) {
            float4 v = src[i];
            float4 w;
            w.x = f2tf(v.x); w.y = f2tf(v.y); w.z = f2tf(v.z); w.w = f2tf(v.w);
            reinterpret_cast<float4*>(xrow + i * 4)[0] = w;
        }
    }
    load_w_tile(Ws, W1, tid, 256);
    __syncthreads();

    float acc[4][8][4];
#pragma unroll
    for (int mt = 0; mt < 4; ++mt)
#pragma unroll
        for (int nt = 0; nt < 8; ++nt)
#pragma unroll
            for (int i = 0; i < 4; ++i) acc[mt][nt][i] = 0.f;

#pragma unroll
    for (int ks = 0; ks < 16; ++ks) {
        const int k0 = ks * 8;
        uint32_t a[4][4];
#pragma unroll
        for (int mt = 0; mt < 4; ++mt) {
            const int r0 = m_warp + mt * 16 + gq;
            a[mt][0] = __float_as_uint(Xs[r0 * LDX + k0 + tq]);
            a[mt][1] = __float_as_uint(Xs[(r0 + 8) * LDX + k0 + tq]);
            a[mt][2] = __float_as_uint(Xs[r0 * LDX + k0 + tq + 4]);
            a[mt][3] = __float_as_uint(Xs[(r0 + 8) * LDX + k0 + tq + 4]);
        }
#pragma unroll
        for (int nt = 0; nt < 8; ++nt) {
            const int n0 = n_warp + nt * 8 + gq;
            const uint32_t b0 = __float_as_uint(Ws[(k0 + tq) * LDW + n0]);
            const uint32_t b1r = __float_as_uint(Ws[(k0 + tq + 4) * LDW + n0]);
#pragma unroll
            for (int mt = 0; mt < 4; ++mt) mma8(acc[mt][nt], a[mt], b0, b1r);
        }
    }

#pragma unroll
    for (int nt = 0; nt < 8; ++nt) {
        const int n0 = n_warp + nt * 8 + tq * 2;
        const float bv0 = b1s[n0], bv1 = b1s[n0 + 1];
#pragma unroll
        for (int mt = 0; mt < 4; ++mt) {
            const int r0 = gbase + m_warp + mt * 16 + gq;
            if (r0 < BN)
                *reinterpret_cast<float2*>(P_buf + (size_t)r0 * 128 + n0) =
                    make_float2(acc[mt][nt][0] + bv0, acc[mt][nt][1] + bv1);
            if (r0 + 8 < BN)
                *reinterpret_cast<float2*>(P_buf + (size_t)(r0 + 8) * 128 + n0) =
                    make_float2(acc[mt][nt][2] + bv0, acc[mt][nt][3] + bv1);
            acc[mt][nt][0] = acc[mt][nt][1] = acc[mt][nt][2] = acc[mt][nt][3] = 0.f;
        }
    }
    __syncthreads();
    load_w_tile(Ws, W1 + 128 * 128, tid, 256);
    __syncthreads();

#pragma unroll
    for (int ks = 0; ks < 16; ++ks) {
        const int k0 = ks * 8;
        uint32_t a[4][4];
#pragma unroll
        for (int mt = 0; mt < 4; ++mt) {
            const int r0 = m_warp + mt * 16 + gq;
            a[mt][0] = __float_as_uint(Xs[r0 * LDX + k0 + tq]);
            a[mt][1] = __float_as_uint(Xs[(r0 + 8) * LDX + k0 + tq]);
            a[mt][2] = __float_as_uint(Xs[r0 * LDX + k0 + tq + 4]);
            a[mt][3] = __float_as_uint(Xs[(r0 + 8) * LDX + k0 + tq + 4]);
        }
#pragma unroll
        for (int nt = 0; nt < 8; ++nt) {
            const int n0 = n_warp + nt * 8 + gq;
            const uint32_t b0 = __float_as_uint(Ws[(k0 + tq) * LDW + n0]);
            const uint32_t b1r = __float_as_uint(Ws[(k0 + tq + 4) * LDW + n0]);
#pragma unroll
            for (int mt = 0; mt < 4; ++mt) mma8(acc[mt][nt], a[mt], b0, b1r);
        }
    }
#pragma unroll
    for (int nt = 0; nt < 8; ++nt) {
        const int n0 = n_warp + nt * 8 + tq * 2;
#pragma unroll
        for (int mt = 0; mt < 4; ++mt) {
            const int r0 = gbase + m_warp + mt * 16 + gq;
            if (r0 < BN)
                *reinterpret_cast<float2*>(Q_buf + (size_t)r0 * 128 + n0) =
                    make_float2(acc[mt][nt][0], acc[mt][nt][1]);
            if (r0 + 8 < BN)
                *reinterpret_cast<float2*>(Q_buf + (size_t)(r0 + 8) * 128 + n0) =
                    make_float2(acc[mt][nt][2], acc[mt][nt][3]);
        }
    }
}

// ================= Kernel 2: edge v3 (2 CTAs/SM) =================
// smem float offsets
#define WSO  0                    // 128*136 = 17408
#define QBO  17408                // 64*132  = 8448
#define SELO 25856                // 64
#define IDXO 25920                // int2[64] = 128 ints
#define SMF  26048                // 104,192 bytes

__global__ void __launch_bounds__(256, 2) edge_kernel(
    const int* __restrict__ edge_index,
    const float* __restrict__ edge_sel,
    const float* __restrict__ W1,
    const float* __restrict__ W2,
    const float* __restrict__ b2,
    float* __restrict__ out,
    int E, int bpb, int n_nodes, int ntiles)
{
    extern __shared__ float smem[];
    float* Ws   = smem + WSO;
    float* QB   = smem + QBO;
    float* sels = smem + SELO;
    int2*  idxs = reinterpret_cast<int2*>(smem + IDXO);
    const uint32_t qb_base = smem_u32(smem) + QBO * 4;

    const int tid  = threadIdx.x;
    const int wid  = tid >> 5;
    const int lane = tid & 31;
    const int gq   = lane >> 2;
    const int tq   = lane & 3;
    const int m_warp = (wid & 1) * 32;     // 2 m-splits (32 rows)
    const int n_warp = (wid >> 1) * 32;    // 4 n-splits (32 cols)

    // per-lane constants in registers
    const float4 w1cv = *reinterpret_cast<const float4*>(W1 + 256 * 128 + lane * 4);
    float b2v[4][2];
#pragma unroll
    for (int nt = 0; nt < 4; ++nt) {
        const int n0 = n_warp + nt * 8 + tq * 2;
        b2v[nt][0] = b2[n0];
        b2v[nt][1] = b2[n0 + 1];
    }

    load_w_tile(Ws, W2, tid, 256);   // one-time

    const int stride = gridDim.x;
    for (int t = blockIdx.x; t < ntiles; t += stride) {
        const int b_idx = t / bpb;
        const long long eb = (long long)b_idx * E + (long long)(t - b_idx * bpb) * 64;
        const size_t rowbase = (size_t)b_idx * n_nodes;

        // ---- idx/sel ----
        __syncthreads();   // QB free (prev STG-phase LDS done)
        if (tid < 64) {
            idxs[tid] = reinterpret_cast<const int2*>(edge_index)[eb + tid];
            sels[tid] = edge_sel[eb + tid];
        }
        __syncthreads();

        // ---- gather: Q -> smem (cp.async), P -> regs (__ldcg) ----
        float4 pv[8];
        {
#pragma unroll
            for (int r = 0; r < 8; ++r) {
                const int row = wid * 8 + r;
                int iv = idxs[row].y;
                iv = min(max(iv, 0), n_nodes - 1);
                cp16(qb_base + (uint32_t)((row * LDX + lane * 4) * 4),
                     Q_buf + (rowbase + iv) * 128 + lane * 4);
            }
            CP_COMMIT();
#pragma unroll
            for (int r = 0; r < 8; ++r) {
                const int row = wid * 8 + r;
                int iu = idxs[row].x;
                iu = min(max(iu, 0), n_nodes - 1);
                pv[r] = __ldcg(reinterpret_cast<const float4*>(
                    P_buf + (rowbase + iu) * 128 + lane * 4));
            }
            CP_WAIT0();
        }
        __syncthreads();

        // ---- combine in place: H = tf32(relu(P + Q + sel*w1c)) over QB ----
#pragma unroll
        for (int r = 0; r < 8; ++r) {
            const int row = wid * 8 + r;
            float4* qp = reinterpret_cast<float4*>(QB + row * LDX + lane * 4);
            const float4 q = *qp;
            const float4 p = pv[r];
            const float s = sels[row];
            float4 h;
            h.x = f2tf(fmaxf(p.x + q.x + s * w1cv.x, 0.f));
            h.y = f2tf(fmaxf(p.y + q.y + s * w1cv.y, 0.f));
            h.z = f2tf(fmaxf(p.z + q.z + s * w1cv.z, 0.f));
            h.w = f2tf(fmaxf(p.w + q.w + s * w1cv.w, 0.f));
            *qp = h;
        }
        __syncthreads();

        // ---- GEMM2: 64x128x128, A = H (QB), B = W2 (Ws) ----
        float acc[2][4][4];
#pragma unroll
        for (int mt = 0; mt < 2; ++mt)
#pragma unroll
            for (int nt = 0; nt < 4; ++nt)
#pragma unroll
                for (int k = 0; k < 4; ++k) acc[mt][nt][k] = 0.f;

#pragma unroll
        for (int ks = 0; ks < 16; ++ks) {
            const int k0 = ks * 8;
            uint32_t a[2][4];
#pragma unroll
            for (int mt = 0; mt < 2; ++mt) {
                const int r0 = m_warp + mt * 16 + gq;
                a[mt][0] = __float_as_uint(QB[r0 * LDX + k0 + tq]);
                a[mt][1] = __float_as_uint(QB[(r0 + 8) * LDX + k0 + tq]);
                a[mt][2] = __float_as_uint(QB[r0 * LDX + k0 + tq + 4]);
                a[mt][3] = __float_as_uint(QB[(r0 + 8) * LDX + k0 + tq + 4]);
            }
#pragma unroll
            for (int nt = 0; nt < 4; ++nt) {
                const int n0 = n_warp + nt * 8 + gq;
                const uint32_t b0 = __float_as_uint(Ws[(k0 + tq) * LDW + n0]);
                const uint32_t b1r = __float_as_uint(Ws[(k0 + tq + 4) * LDW + n0]);
                mma8(acc[0][nt], a[0], b0, b1r);
                mma8(acc[1][nt], a[1], b0, b1r);
            }
        }
        __syncthreads();   // all A reads done before Os overwrites QB

        // ---- epilogue: relu(acc+b2) -> QB (as Os), then coalesced STG.cs ----
#pragma unroll
        for (int nt = 0; nt < 4; ++nt) {
            const int n0 = n_warp + nt * 8 + tq * 2;
#pragma unroll
            for (int mt = 0; mt < 2; ++mt) {
                const int r0 = m_warp + mt * 16 + gq;
                *reinterpret_cast<float2*>(QB + r0 * LDX + n0) =
                    make_float2(fmaxf(acc[mt][nt][0] + b2v[nt][0], 0.f),
                                fmaxf(acc[mt][nt][1] + b2v[nt][1], 0.f));
                *reinterpret_cast<float2*>(QB + (r0 + 8) * LDX + n0) =
                    make_float2(fmaxf(acc[mt][nt][2] + b2v[nt][0], 0.f),
                                fmaxf(acc[mt][nt][3] + b2v[nt][1], 0.f));
            }
        }
        __syncthreads();
#pragma unroll
        for (int j = 0; j < 8; ++j) {
            const int row = j * 8 + wid;
            const float4 v = reinterpret_cast<const float4*>(QB + row * LDX)[lane];
            __stcs(reinterpret_cast<float4*>(out + (size_t)(eb + row) * 128) + lane, v);
        }
    }
}

extern "C" void kernel_launch(void* const* d_in, const int* in_sizes, int n_in,
                              void* d_out, int out_size) {
    const float* node_emb   = (const float*)d_in[0];
    const int*   edge_index = (const int*)d_in[1];   // int32
    const float* edge_sel   = (const float*)d_in[2];
    const float* W1         = (const float*)d_in[3];
    const float* b1         = (const float*)d_in[4];
    const float* W2         = (const float*)d_in[5];
    const float* b2         = (const float*)d_in[6];
    float*       out        = (float*)d_out;

    const int B  = 4;
    const int E  = in_sizes[2] / B;
    const int n_nodes = in_sizes[0] / (B * 128);
    const int BN = B * n_nodes;

    const int grid1 = (BN + 255) / 256;
    const int bpb   = E / 64;
    const int ntiles = B * bpb;

    int dev = 0, sms = 148;
    cudaGetDevice(&dev);
    cudaDeviceGetAttribute(&sms, cudaDevAttrMultiProcessorCount, dev);
    int grid2 = 2 * sms;
    if (grid2 > ntiles) grid2 = ntiles;

    const size_t smem1 = (size_t)(256 * LDX + 128 * LDW + 128) * sizeof(float);
    const size_t smem2 = (size_t)SMF * sizeof(float);
    cudaFuncSetAttribute(node_proj_kernel,
                         cudaFuncAttributeMaxDynamicSharedMemorySize, (int)smem1);
    cudaFuncSetAttribute(edge_kernel,
                         cudaFuncAttributeMaxDynamicSharedMemorySize, (int)smem2);

    node_proj_kernel<<<grid1, 256, smem1>>>(node_emb, W1, b1, BN);
    edge_kernel<<<grid2, 256, smem2>>>(edge_index, edge_sel, W1, W2, b2, out,
                                       E, bpb, n_nodes, ntiles);
}

// round 11
// speedup vs baseline: 2.1684x; 1.4828x over previous
#include <cuda_runtime.h>
#include <cuda_fp16.h>
#include <cstdint>
#include <cstddef>

// EdgeEncoder:
//   K1 (proj): P = f16(node_emb)@f16(W1a)+b1 ; Q = f16(node_emb)@f16(W1b)  [fp32 accum, P/Q fp32]
//   K2 (edge): 2 CTAs/SM persistent. P->regs (__ldcg), Q->smem (cp.async),
//              H = f16(relu(P+Q+sel*w1c)); out = relu(H@f16(W2)+b2), staged STG.cs.
// fp16 mma m16n8k16 (10 mantissa bits == tf32 rounding class). edge_index is int32.

#define LDX 132    // fp32 QB row stride (floats)
#define LDH 136    // fp16 row stride (halves) -> 272B, conflict-free frags

#define MAXROWS 401408
__device__ float P_buf[(size_t)MAXROWS * 128];
__device__ float Q_buf[(size_t)MAXROWS * 128];

__device__ __forceinline__ uint32_t pack2(float a, float b) {
    half2 h = __floats2half2_rn(a, b);
    return *reinterpret_cast<uint32_t*>(&h);
}
__device__ __forceinline__ uint32_t smem_u32(const void* p) {
    uint32_t a;
    asm("{ .reg .u64 t; cvta.to.shared.u64 t, %1; cvt.u32.u64 %0, t; }" : "=r"(a) : "l"(p));
    return a;
}
__device__ __forceinline__ void cp16(uint32_t dst, const void* src) {
    asm volatile("cp.async.cg.shared.global [%0], [%1], 16;" :: "r"(dst), "l"(src));
}
#define CP_COMMIT() asm volatile("cp.async.commit_group;" ::: "memory")
#define CP_WAIT0()  asm volatile("cp.async.wait_group 0;" ::: "memory")

__device__ __forceinline__ void mma16(float c[4], const uint32_t a[4], uint32_t b0, uint32_t b1) {
    asm("mma.sync.aligned.m16n8k16.row.col.f32.f16.f16.f32 "
        "{%0,%1,%2,%3}, {%4,%5,%6,%7}, {%8,%9}, {%0,%1,%2,%3};"
        : "+f"(c[0]), "+f"(c[1]), "+f"(c[2]), "+f"(c[3])
        : "r"(a[0]), "r"(a[1]), "r"(a[2]), "r"(a[3]), "r"(b0), "r"(b1));
}
__device__ __forceinline__ uint32_t lds32(const half* p) {
    return *reinterpret_cast<const uint32_t*>(p);
}

// Load W[128k x 128n] (fp32 row-major) transposed into WsT[n][k] fp16, LDH stride.
// n = tid&127, kh = tid>>7 covers k-half; LDG coalesced along n, STS.128 conflict-free per phase.
__device__ __forceinline__ void load_wT(half* __restrict__ WsT,
                                        const float* __restrict__ src, int tid) {
    const int n = tid & 127, kh = tid >> 7;
#pragma unroll
    for (int g = 0; g < 8; ++g) {
        const int kb = kh * 64 + g * 8;
        uint4 u;
        u.x = pack2(src[(kb + 0) * 128 + n], src[(kb + 1) * 128 + n]);
        u.y = pack2(src[(kb + 2) * 128 + n], src[(kb + 3) * 128 + n]);
        u.z = pack2(src[(kb + 4) * 128 + n], src[(kb + 5) * 128 + n]);
        u.w = pack2(src[(kb + 6) * 128 + n], src[(kb + 7) * 128 + n]);
        *reinterpret_cast<uint4*>(WsT + n * LDH + kb) = u;
    }
}

// ================= Kernel 1: node projections (fp16 mma, 128-row tiles, 2 CTAs/SM) ==========
__global__ void __launch_bounds__(256, 2) node_proj_kernel(
    const float* __restrict__ node_emb,
    const float* __restrict__ W1,
    const float* __restrict__ b1,
    int BN)
{
    extern __shared__ char smc[];
    half* XsH  = reinterpret_cast<half*>(smc);                    // 128*LDH halves
    half* WsT  = reinterpret_cast<half*>(smc) + 128 * LDH;        // 128*LDH halves

    const int tid  = threadIdx.x;
    const int wid  = tid >> 5;
    const int lane = tid & 31;
    const int gq   = lane >> 2;
    const int tq   = lane & 3;
    const int m_warp = (wid & 1) * 64;     // 2 m-splits of 64
    const int n_warp = (wid >> 1) * 32;    // 4 n-splits of 32
    const int gbase = blockIdx.x * 128;

    // bias regs
    float b1v[4][2];
#pragma unroll
    for (int nt = 0; nt < 4; ++nt) {
        const int n0 = n_warp + nt * 8 + tq * 2;
        b1v[nt][0] = b1[n0];
        b1v[nt][1] = b1[n0 + 1];
    }

    // X tile -> fp16 smem (2 thr/row)
    {
        const int row = tid >> 1, h = tid & 1;
        int g = gbase + row;
        if (g >= BN) g = BN - 1;
        const float4* src = reinterpret_cast<const float4*>(node_emb + (size_t)g * 128 + h * 64);
        half* xrow = XsH + row * LDH + h * 64;
#pragma unroll
        for (int i = 0; i < 16; ++i) {
            const float4 v = src[i];
            *reinterpret_cast<uint2*>(xrow + i * 4) = make_uint2(pack2(v.x, v.y), pack2(v.z, v.w));
        }
    }
    load_wT(WsT, W1, tid);                 // W1a^T
    __syncthreads();

    float acc[4][4][4];
#pragma unroll
    for (int mt = 0; mt < 4; ++mt)
#pragma unroll
        for (int nt = 0; nt < 4; ++nt)
#pragma unroll
            for (int i = 0; i < 4; ++i) acc[mt][nt][i] = 0.f;

#pragma unroll
    for (int ks = 0; ks < 8; ++ks) {
        const int k0 = ks * 16;
        uint32_t a[4][4];
#pragma unroll
        for (int mt = 0; mt < 4; ++mt) {
            const int r0 = m_warp + mt * 16 + gq;
            a[mt][0] = lds32(XsH + r0 * LDH + k0 + 2 * tq);
            a[mt][1] = lds32(XsH + (r0 + 8) * LDH + k0 + 2 * tq);
            a[mt][2] = lds32(XsH + r0 * LDH + k0 + 8 + 2 * tq);
            a[mt][3] = lds32(XsH + (r0 + 8) * LDH + k0 + 8 + 2 * tq);
        }
#pragma unroll
        for (int nt = 0; nt < 4; ++nt) {
            const int n0 = n_warp + nt * 8 + gq;
            const uint32_t b0 = lds32(WsT + n0 * LDH + k0 + 2 * tq);
            const uint32_t b1r = lds32(WsT + n0 * LDH + k0 + 8 + 2 * tq);
#pragma unroll
            for (int mt = 0; mt < 4; ++mt) mma16(acc[mt][nt], a[mt], b0, b1r);
        }
    }

    // store P = acc + b1
#pragma unroll
    for (int nt = 0; nt < 4; ++nt) {
        const int n0 = n_warp + nt * 8 + tq * 2;
#pragma unroll
        for (int mt = 0; mt < 4; ++mt) {
            const int r0 = gbase + m_warp + mt * 16 + gq;
            if (r0 < BN)
                *reinterpret_cast<float2*>(P_buf + (size_t)r0 * 128 + n0) =
                    make_float2(acc[mt][nt][0] + b1v[nt][0], acc[mt][nt][1] + b1v[nt][1]);
            if (r0 + 8 < BN)
                *reinterpret_cast<float2*>(P_buf + (size_t)(r0 + 8) * 128 + n0) =
                    make_float2(acc[mt][nt][2] + b1v[nt][0], acc[mt][nt][3] + b1v[nt][1]);
            acc[mt][nt][0] = acc[mt][nt][1] = acc[mt][nt][2] = acc[mt][nt][3] = 0.f;
        }
    }
    __syncthreads();
    load_wT(WsT, W1 + 128 * 128, tid);     // W1b^T
    __syncthreads();

#pragma unroll
    for (int ks = 0; ks < 8; ++ks) {
        const int k0 = ks * 16;
        uint32_t a[4][4];
#pragma unroll
        for (int mt = 0; mt < 4; ++mt) {
            const int r0 = m_warp + mt * 16 + gq;
            a[mt][0] = lds32(XsH + r0 * LDH + k0 + 2 * tq);
            a[mt][1] = lds32(XsH + (r0 + 8) * LDH + k0 + 2 * tq);
            a[mt][2] = lds32(XsH + r0 * LDH + k0 + 8 + 2 * tq);
            a[mt][3] = lds32(XsH + (r0 + 8) * LDH + k0 + 8 + 2 * tq);
        }
#pragma unroll
        for (int nt = 0; nt < 4; ++nt) {
            const int n0 = n_warp + nt * 8 + gq;
            const uint32_t b0 = lds32(WsT + n0 * LDH + k0 + 2 * tq);
            const uint32_t b1r = lds32(WsT + n0 * LDH + k0 + 8 + 2 * tq);
#pragma unroll
            for (int mt = 0; mt < 4; ++mt) mma16(acc[mt][nt], a[mt], b0, b1r);
        }
    }
#pragma unroll
    for (int nt = 0; nt < 4; ++nt) {
        const int n0 = n_warp + nt * 8 + tq * 2;
#pragma unroll
        for (int mt = 0; mt < 4; ++mt) {
            const int r0 = gbase + m_warp + mt * 16 + gq;
            if (r0 < BN)
                *reinterpret_cast<float2*>(Q_buf + (size_t)r0 * 128 + n0) =
                    make_float2(acc[mt][nt][0], acc[mt][nt][1]);
            if (r0 + 8 < BN)
                *reinterpret_cast<float2*>(Q_buf + (size_t)(r0 + 8) * 128 + n0) =
                    make_float2(acc[mt][nt][2], acc[mt][nt][3]);
        }
    }
}

// ================= Kernel 2: edge (fp16 GEMM2, 2 CTAs/SM) =================
// smem byte offsets
#define E_WT   0                          // WsT: 128*LDH*2 = 34816
#define E_QB   34816                      // QB fp32: 64*LDX*4 = 33792
#define E_HB   68608                      // HB fp16: 64*LDH*2 = 17408
#define E_SEL  86016                      // 64 floats
#define E_IDX  86272                      // 64 int2
#define E_SMB  86784

__global__ void __launch_bounds__(256, 2) edge_kernel(
    const int* __restrict__ edge_index,
    const float* __restrict__ edge_sel,
    const float* __restrict__ W1,
    const float* __restrict__ W2,
    const float* __restrict__ b2,
    float* __restrict__ out,
    int E, int bpb, int n_nodes, int ntiles)
{
    extern __shared__ char smc[];
    half*  WsT  = reinterpret_cast<half*>(smc + E_WT);
    float* QB   = reinterpret_cast<float*>(smc + E_QB);
    half*  HB   = reinterpret_cast<half*>(smc + E_HB);
    float* sels = reinterpret_cast<float*>(smc + E_SEL);
    int2*  idxs = reinterpret_cast<int2*>(smc + E_IDX);
    const uint32_t qb_base = smem_u32(smc) + E_QB;

    const int tid  = threadIdx.x;
    const int wid  = tid >> 5;
    const int lane = tid & 31;
    const int gq   = lane >> 2;
    const int tq   = lane & 3;
    const int m_warp = (wid & 1) * 32;     // 2 m-splits
    const int n_warp = (wid >> 1) * 32;    // 4 n-splits

    const float4 w1cv = *reinterpret_cast<const float4*>(W1 + 256 * 128 + lane * 4);
    float b2v[4][2];
#pragma unroll
    for (int nt = 0; nt < 4; ++nt) {
        const int n0 = n_warp + nt * 8 + tq * 2;
        b2v[nt][0] = b2[n0];
        b2v[nt][1] = b2[n0 + 1];
    }

    load_wT(WsT, W2, tid);   // one-time W2^T

    const int stride = gridDim.x;
    for (int t = blockIdx.x; t < ntiles; t += stride) {
        const int b_idx = t / bpb;
        const long long eb = (long long)b_idx * E + (long long)(t - b_idx * bpb) * 64;
        const size_t rowbase = (size_t)b_idx * n_nodes;

        __syncthreads();
        if (tid < 64) {
            idxs[tid] = reinterpret_cast<const int2*>(edge_index)[eb + tid];
            sels[tid] = edge_sel[eb + tid];
        }
        __syncthreads();

        // gather: Q -> smem (cp.async), P -> regs
        float4 pv[8];
        {
#pragma unroll
            for (int r = 0; r < 8; ++r) {
                const int row = wid * 8 + r;
                int iv = idxs[row].y;
                iv = min(max(iv, 0), n_nodes - 1);
                cp16(qb_base + (uint32_t)((row * LDX + lane * 4) * 4),
                     Q_buf + (rowbase + iv) * 128 + lane * 4);
            }
            CP_COMMIT();
#pragma unroll
            for (int r = 0; r < 8; ++r) {
                const int row = wid * 8 + r;
                int iu = idxs[row].x;
                iu = min(max(iu, 0), n_nodes - 1);
                pv[r] = __ldcg(reinterpret_cast<const float4*>(
                    P_buf + (rowbase + iu) * 128 + lane * 4));
            }
            CP_WAIT0();
        }
        __syncthreads();

        // combine: H = f16(relu(P + Q + sel*w1c)) -> HB
#pragma unroll
        for (int r = 0; r < 8; ++r) {
            const int row = wid * 8 + r;
            const float4 q = *reinterpret_cast<const float4*>(QB + row * LDX + lane * 4);
            const float4 p = pv[r];
            const float s = sels[row];
            *reinterpret_cast<uint2*>(HB + row * LDH + lane * 4) = make_uint2(
                pack2(fmaxf(p.x + q.x + s * w1cv.x, 0.f),
                      fmaxf(p.y + q.y + s * w1cv.y, 0.f)),
                pack2(fmaxf(p.z + q.z + s * w1cv.z, 0.f),
                      fmaxf(p.w + q.w + s * w1cv.w, 0.f)));
        }
        __syncthreads();

        // GEMM2: 64x128x128 fp16, A = HB, B = WsT
        float acc[2][4][4];
#pragma unroll
        for (int mt = 0; mt < 2; ++mt)
#pragma unroll
            for (int nt = 0; nt < 4; ++nt)
#pragma unroll
                for (int k = 0; k < 4; ++k) acc[mt][nt][k] = 0.f;

#pragma unroll
        for (int ks = 0; ks < 8; ++ks) {
            const int k0 = ks * 16;
            uint32_t a[2][4];
#pragma unroll
            for (int mt = 0; mt < 2; ++mt) {
                const int r0 = m_warp + mt * 16 + gq;
                a[mt][0] = lds32(HB + r0 * LDH + k0 + 2 * tq);
                a[mt][1] = lds32(HB + (r0 + 8) * LDH + k0 + 2 * tq);
                a[mt][2] = lds32(HB + r0 * LDH + k0 + 8 + 2 * tq);
                a[mt][3] = lds32(HB + (r0 + 8) * LDH + k0 + 8 + 2 * tq);
            }
#pragma unroll
            for (int nt = 0; nt < 4; ++nt) {
                const int n0 = n_warp + nt * 8 + gq;
                const uint32_t b0 = lds32(WsT + n0 * LDH + k0 + 2 * tq);
                const uint32_t b1r = lds32(WsT + n0 * LDH + k0 + 8 + 2 * tq);
                mma16(acc[0][nt], a[0], b0, b1r);
                mma16(acc[1][nt], a[1], b0, b1r);
            }
        }
        __syncthreads();

        // epilogue: relu(acc+b2) -> QB (staging), then coalesced STG.cs
#pragma unroll
        for (int nt = 0; nt < 4; ++nt) {
            const int n0 = n_warp + nt * 8 + tq * 2;
#pragma unroll
            for (int mt = 0; mt < 2; ++mt) {
                const int r0 = m_warp + mt * 16 + gq;
                *reinterpret_cast<float2*>(QB + r0 * LDX + n0) =
                    make_float2(fmaxf(acc[mt][nt][0] + b2v[nt][0], 0.f),
                                fmaxf(acc[mt][nt][1] + b2v[nt][1], 0.f));
                *reinterpret_cast<float2*>(QB + (r0 + 8) * LDX + n0) =
                    make_float2(fmaxf(acc[mt][nt][2] + b2v[nt][0], 0.f),
                                fmaxf(acc[mt][nt][3] + b2v[nt][1], 0.f));
            }
        }
        __syncthreads();
#pragma unroll
        for (int j = 0; j < 8; ++j) {
            const int row = j * 8 + wid;
            const float4 v = reinterpret_cast<const float4*>(QB + row * LDX)[lane];
            __stcs(reinterpret_cast<float4*>(out + (size_t)(eb + row) * 128) + lane, v);
        }
    }
}

extern "C" void kernel_launch(void* const* d_in, const int* in_sizes, int n_in,
                              void* d_out, int out_size) {
    const float* node_emb   = (const float*)d_in[0];
    const int*   edge_index = (const int*)d_in[1];   // int32
    const float* edge_sel   = (const float*)d_in[2];
    const float* W1         = (const float*)d_in[3];
    const float* b1         = (const float*)d_in[4];
    const float* W2         = (const float*)d_in[5];
    const float* b2         = (const float*)d_in[6];
    float*       out        = (float*)d_out;

    const int B  = 4;
    const int E  = in_sizes[2] / B;
    const int n_nodes = in_sizes[0] / (B * 128);
    const int BN = B * n_nodes;

    const int grid1 = (BN + 127) / 128;
    const int bpb   = E / 64;
    const int ntiles = B * bpb;

    int dev = 0, sms = 148;
    cudaGetDevice(&dev);
    cudaDeviceGetAttribute(&sms, cudaDevAttrMultiProcessorCount, dev);
    int grid2 = 2 * sms;
    if (grid2 > ntiles) grid2 = ntiles;

    const size_t smem1 = (size_t)(256 * LDH) * sizeof(half);   // Xs(128*LDH) + WsT(128*LDH)
    const size_t smem2 = (size_t)E_SMB;
    cudaFuncSetAttribute(node_proj_kernel,
                         cudaFuncAttributeMaxDynamicSharedMemorySize, (int)smem1);
    cudaFuncSetAttribute(edge_kernel,
                         cudaFuncAttributeMaxDynamicSharedMemorySize, (int)smem2);

    node_proj_kernel<<<grid1, 256, smem1>>>(node_emb, W1, b1, BN);
    edge_kernel<<<grid2, 256, smem2>>>(edge_index, edge_sel, W1, W2, b2, out,
                                       E, bpb, n_nodes, ntiles);
}

// round 12
// speedup vs baseline: 2.3476x; 1.0826x over previous
#include <cuda_runtime.h>
#include <cuda_fp16.h>
#include <cstdint>
#include <cstddef>

// EdgeEncoder:
//   K1 (proj): P = f16(node_emb)@f16(W1a)+b1 ; Q = f16(node_emb)@f16(W1b)  [fp32 accum, P/Q stored fp16]
//   K2 (edge): 2 CTAs/SM persistent. P->regs (__ldcg uint4), Q->smem (cp.async),
//              H = f16(relu(P+Q+sel*w1c)); out = relu(H@f16(W2)+b2), staged STG.cs.
// fp16 mma m16n8k16. edge_index is int32.

#define LDX 132    // fp32 staging row stride (floats)
#define LDH 136    // fp16 row stride (halves) -> 272B

#define MAXROWS 401408
__device__ half P_buf[(size_t)MAXROWS * 128];
__device__ half Q_buf[(size_t)MAXROWS * 128];

__device__ __forceinline__ uint32_t pack2(float a, float b) {
    half2 h = __floats2half2_rn(a, b);
    return *reinterpret_cast<uint32_t*>(&h);
}
__device__ __forceinline__ float2 unpack2(uint32_t u) {
    return __half22float2(*reinterpret_cast<half2*>(&u));
}
__device__ __forceinline__ uint32_t smem_u32(const void* p) {
    uint32_t a;
    asm("{ .reg .u64 t; cvta.to.shared.u64 t, %1; cvt.u32.u64 %0, t; }" : "=r"(a) : "l"(p));
    return a;
}
__device__ __forceinline__ void cp16(uint32_t dst, const void* src) {
    asm volatile("cp.async.cg.shared.global [%0], [%1], 16;" :: "r"(dst), "l"(src));
}
#define CP_COMMIT() asm volatile("cp.async.commit_group;" ::: "memory")
#define CP_WAIT0()  asm volatile("cp.async.wait_group 0;" ::: "memory")

__device__ __forceinline__ void mma16(float c[4], const uint32_t a[4], uint32_t b0, uint32_t b1) {
    asm("mma.sync.aligned.m16n8k16.row.col.f32.f16.f16.f32 "
        "{%0,%1,%2,%3}, {%4,%5,%6,%7}, {%8,%9}, {%0,%1,%2,%3};"
        : "+f"(c[0]), "+f"(c[1]), "+f"(c[2]), "+f"(c[3])
        : "r"(a[0]), "r"(a[1]), "r"(a[2]), "r"(a[3]), "r"(b0), "r"(b1));
}
__device__ __forceinline__ uint32_t lds32(const half* p) {
    return *reinterpret_cast<const uint32_t*>(p);
}

// W[128k x 128n] fp32 row-major -> WsT[n][k] fp16, LDH stride.
__device__ __forceinline__ void load_wT(half* __restrict__ WsT,
                                        const float* __restrict__ src, int tid) {
    const int n = tid & 127, kh = tid >> 7;
#pragma unroll
    for (int g = 0; g < 8; ++g) {
        const int kb = kh * 64 + g * 8;
        uint4 u;
        u.x = pack2(src[(kb + 0) * 128 + n], src[(kb + 1) * 128 + n]);
        u.y = pack2(src[(kb + 2) * 128 + n], src[(kb + 3) * 128 + n]);
        u.z = pack2(src[(kb + 4) * 128 + n], src[(kb + 5) * 128 + n]);
        u.w = pack2(src[(kb + 6) * 128 + n], src[(kb + 7) * 128 + n]);
        *reinterpret_cast<uint4*>(WsT + n * LDH + kb) = u;
    }
}

// ================= Kernel 1: node projections (fp16 mma, 128-row tiles, 2 CTAs/SM) ==========
__global__ void __launch_bounds__(256, 2) node_proj_kernel(
    const float* __restrict__ node_emb,
    const float* __restrict__ W1,
    const float* __restrict__ b1,
    int BN)
{
    extern __shared__ char smc[];
    half* XsH  = reinterpret_cast<half*>(smc);                    // 128*LDH
    half* WsT  = reinterpret_cast<half*>(smc) + 128 * LDH;        // 128*LDH

    const int tid  = threadIdx.x;
    const int wid  = tid >> 5;
    const int lane = tid & 31;
    const int gq   = lane >> 2;
    const int tq   = lane & 3;
    const int m_warp = (wid & 1) * 64;
    const int n_warp = (wid >> 1) * 32;
    const int gbase = blockIdx.x * 128;

    float b1v[4][2];
#pragma unroll
    for (int nt = 0; nt < 4; ++nt) {
        const int n0 = n_warp + nt * 8 + tq * 2;
        b1v[nt][0] = b1[n0];
        b1v[nt][1] = b1[n0 + 1];
    }

    {
        const int row = tid >> 1, h = tid & 1;
        int g = gbase + row;
        if (g >= BN) g = BN - 1;
        const float4* src = reinterpret_cast<const float4*>(node_emb + (size_t)g * 128 + h * 64);
        half* xrow = XsH + row * LDH + h * 64;
#pragma unroll
        for (int i = 0; i < 16; ++i) {
            const float4 v = src[i];
            *reinterpret_cast<uint2*>(xrow + i * 4) = make_uint2(pack2(v.x, v.y), pack2(v.z, v.w));
        }
    }
    load_wT(WsT, W1, tid);                 // W1a^T
    __syncthreads();

    float acc[4][4][4];
#pragma unroll
    for (int mt = 0; mt < 4; ++mt)
#pragma unroll
        for (int nt = 0; nt < 4; ++nt)
#pragma unroll
            for (int i = 0; i < 4; ++i) acc[mt][nt][i] = 0.f;

#pragma unroll
    for (int ks = 0; ks < 8; ++ks) {
        const int k0 = ks * 16;
        uint32_t a[4][4];
#pragma unroll
        for (int mt = 0; mt < 4; ++mt) {
            const int r0 = m_warp + mt * 16 + gq;
            a[mt][0] = lds32(XsH + r0 * LDH + k0 + 2 * tq);
            a[mt][1] = lds32(XsH + (r0 + 8) * LDH + k0 + 2 * tq);
            a[mt][2] = lds32(XsH + r0 * LDH + k0 + 8 + 2 * tq);
            a[mt][3] = lds32(XsH + (r0 + 8) * LDH + k0 + 8 + 2 * tq);
        }
#pragma unroll
        for (int nt = 0; nt < 4; ++nt) {
            const int n0 = n_warp + nt * 8 + gq;
            const uint32_t b0 = lds32(WsT + n0 * LDH + k0 + 2 * tq);
            const uint32_t b1r = lds32(WsT + n0 * LDH + k0 + 8 + 2 * tq);
#pragma unroll
            for (int mt = 0; mt < 4; ++mt) mma16(acc[mt][nt], a[mt], b0, b1r);
        }
    }

    // store P = f16(acc + b1)
#pragma unroll
    for (int nt = 0; nt < 4; ++nt) {
        const int n0 = n_warp + nt * 8 + tq * 2;
#pragma unroll
        for (int mt = 0; mt < 4; ++mt) {
            const int r0 = gbase + m_warp + mt * 16 + gq;
            if (r0 < BN)
                *reinterpret_cast<uint32_t*>(P_buf + (size_t)r0 * 128 + n0) =
                    pack2(acc[mt][nt][0] + b1v[nt][0], acc[mt][nt][1] + b1v[nt][1]);
            if (r0 + 8 < BN)
                *reinterpret_cast<uint32_t*>(P_buf + (size_t)(r0 + 8) * 128 + n0) =
                    pack2(acc[mt][nt][2] + b1v[nt][0], acc[mt][nt][3] + b1v[nt][1]);
            acc[mt][nt][0] = acc[mt][nt][1] = acc[mt][nt][2] = acc[mt][nt][3] = 0.f;
        }
    }
    __syncthreads();
    load_wT(WsT, W1 + 128 * 128, tid);     // W1b^T
    __syncthreads();

#pragma unroll
    for (int ks = 0; ks < 8; ++ks) {
        const int k0 = ks * 16;
        uint32_t a[4][4];
#pragma unroll
        for (int mt = 0; mt < 4; ++mt) {
            const int r0 = m_warp + mt * 16 + gq;
            a[mt][0] = lds32(XsH + r0 * LDH + k0 + 2 * tq);
            a[mt][1] = lds32(XsH + (r0 + 8) * LDH + k0 + 2 * tq);
            a[mt][2] = lds32(XsH + r0 * LDH + k0 + 8 + 2 * tq);
            a[mt][3] = lds32(XsH + (r0 + 8) * LDH + k0 + 8 + 2 * tq);
        }
#pragma unroll
        for (int nt = 0; nt < 4; ++nt) {
            const int n0 = n_warp + nt * 8 + gq;
            const uint32_t b0 = lds32(WsT + n0 * LDH + k0 + 2 * tq);
            const uint32_t b1r = lds32(WsT + n0 * LDH + k0 + 8 + 2 * tq);
#pragma unroll
            for (int mt = 0; mt < 4; ++mt) mma16(acc[mt][nt], a[mt], b0, b1r);
        }
    }
#pragma unroll
    for (int nt = 0; nt < 4; ++nt) {
        const int n0 = n_warp + nt * 8 + tq * 2;
#pragma unroll
        for (int mt = 0; mt < 4; ++mt) {
            const int r0 = gbase + m_warp + mt * 16 + gq;
            if (r0 < BN)
                *reinterpret_cast<uint32_t*>(Q_buf + (size_t)r0 * 128 + n0) =
                    pack2(acc[mt][nt][0], acc[mt][nt][1]);
            if (r0 + 8 < BN)
                *reinterpret_cast<uint32_t*>(Q_buf + (size_t)(r0 + 8) * 128 + n0) =
                    pack2(acc[mt][nt][2], acc[mt][nt][3]);
        }
    }
}

// ================= Kernel 2: edge (fp16 P/Q gather, 2 CTAs/SM) =================
// smem byte offsets
#define E_WT   0                          // WsT: 34816
#define E_QB   34816                      // QB fp16: 64*LDH*2 = 17408
#define E_HB   52224                      // HB fp16: 17408   (ends 69632)
#define E_OS   34816                      // OS fp32 aliases QB+HB (33792 <= 34816)
#define E_SEL  69632                      // 64 floats
#define E_IDX  69888                      // 64 int2
#define E_SMB  70400

__global__ void __launch_bounds__(256, 2) edge_kernel(
    const int* __restrict__ edge_index,
    const float* __restrict__ edge_sel,
    const float* __restrict__ W1,
    const float* __restrict__ W2,
    const float* __restrict__ b2,
    float* __restrict__ out,
    int E, int bpb, int n_nodes, int ntiles)
{
    extern __shared__ char smc[];
    half*  WsT  = reinterpret_cast<half*>(smc + E_WT);
    half*  QBh  = reinterpret_cast<half*>(smc + E_QB);
    half*  HB   = reinterpret_cast<half*>(smc + E_HB);
    float* OS   = reinterpret_cast<float*>(smc + E_OS);
    float* sels = reinterpret_cast<float*>(smc + E_SEL);
    int2*  idxs = reinterpret_cast<int2*>(smc + E_IDX);
    const uint32_t qb_base = smem_u32(smc) + E_QB;

    const int tid  = threadIdx.x;
    const int wid  = tid >> 5;
    const int lane = tid & 31;
    const int gq   = lane >> 2;
    const int tq   = lane & 3;
    const int m_warp = (wid & 1) * 32;
    const int n_warp = (wid >> 1) * 32;

    // gather mapping: 2 rows per warp-pass, 16 lanes x 16B each
    const int rsub  = lane >> 4;          // 0/1: which row of the pair
    const int chunk = lane & 15;          // 16B chunk within 256B row

    // w1c for this thread's 8 columns
    float w1cv8[8];
#pragma unroll
    for (int j = 0; j < 8; ++j) w1cv8[j] = W1[256 * 128 + chunk * 8 + j];

    float b2v[4][2];
#pragma unroll
    for (int nt = 0; nt < 4; ++nt) {
        const int n0 = n_warp + nt * 8 + tq * 2;
        b2v[nt][0] = b2[n0];
        b2v[nt][1] = b2[n0 + 1];
    }

    load_wT(WsT, W2, tid);   // one-time W2^T

    const int stride = gridDim.x;
    for (int t = blockIdx.x; t < ntiles; t += stride) {
        const int b_idx = t / bpb;
        const long long eb = (long long)b_idx * E + (long long)(t - b_idx * bpb) * 64;
        const size_t rowbase = (size_t)b_idx * n_nodes;

        __syncthreads();
        if (tid < 64) {
            idxs[tid] = reinterpret_cast<const int2*>(edge_index)[eb + tid];
            sels[tid] = edge_sel[eb + tid];
        }
        __syncthreads();

        // gather: Q -> smem (cp.async, fp16), P -> regs (__ldcg uint4)
        uint4 pv[4];
        {
#pragma unroll
            for (int r = 0; r < 4; ++r) {
                const int row = wid * 8 + 2 * r + rsub;
                int iv = idxs[row].y;
                iv = min(max(iv, 0), n_nodes - 1);
                cp16(qb_base + (uint32_t)((row * LDH + chunk * 8) * 2),
                     Q_buf + (rowbase + iv) * 128 + chunk * 8);
            }
            CP_COMMIT();
#pragma unroll
            for (int r = 0; r < 4; ++r) {
                const int row = wid * 8 + 2 * r + rsub;
                int iu = idxs[row].x;
                iu = min(max(iu, 0), n_nodes - 1);
                pv[r] = __ldcg(reinterpret_cast<const uint4*>(
                    P_buf + (rowbase + iu) * 128 + chunk * 8));
            }
            CP_WAIT0();
        }
        __syncthreads();

        // combine: H = f16(relu(P + Q + sel*w1c)) -> HB
#pragma unroll
        for (int r = 0; r < 4; ++r) {
            const int row = wid * 8 + 2 * r + rsub;
            const uint4 q = *reinterpret_cast<const uint4*>(QBh + row * LDH + chunk * 8);
            const uint4 p = pv[r];
            const float s = sels[row];
            const float2 p0 = unpack2(p.x), p1 = unpack2(p.y), p2 = unpack2(p.z), p3 = unpack2(p.w);
            const float2 q0 = unpack2(q.x), q1 = unpack2(q.y), q2 = unpack2(q.z), q3 = unpack2(q.w);
            uint4 h;
            h.x = pack2(fmaxf(p0.x + q0.x + s * w1cv8[0], 0.f),
                        fmaxf(p0.y + q0.y + s * w1cv8[1], 0.f));
            h.y = pack2(fmaxf(p1.x + q1.x + s * w1cv8[2], 0.f),
                        fmaxf(p1.y + q1.y + s * w1cv8[3], 0.f));
            h.z = pack2(fmaxf(p2.x + q2.x + s * w1cv8[4], 0.f),
                        fmaxf(p2.y + q2.y + s * w1cv8[5], 0.f));
            h.w = pack2(fmaxf(p3.x + q3.x + s * w1cv8[6], 0.f),
                        fmaxf(p3.y + q3.y + s * w1cv8[7], 0.f));
            *reinterpret_cast<uint4*>(HB + row * LDH + chunk * 8) = h;
        }
        __syncthreads();

        // GEMM2: 64x128x128 fp16, A = HB, B = WsT
        float acc[2][4][4];
#pragma unroll
        for (int mt = 0; mt < 2; ++mt)
#pragma unroll
            for (int nt = 0; nt < 4; ++nt)
#pragma unroll
                for (int k = 0; k < 4; ++k) acc[mt][nt][k] = 0.f;

#pragma unroll
        for (int ks = 0; ks < 8; ++ks) {
            const int k0 = ks * 16;
            uint32_t a[2][4];
#pragma unroll
            for (int mt = 0; mt < 2; ++mt) {
                const int r0 = m_warp + mt * 16 + gq;
                a[mt][0] = lds32(HB + r0 * LDH + k0 + 2 * tq);
                a[mt][1] = lds32(HB + (r0 + 8) * LDH + k0 + 2 * tq);
                a[mt][2] = lds32(HB + r0 * LDH + k0 + 8 + 2 * tq);
                a[mt][3] = lds32(HB + (r0 + 8) * LDH + k0 + 8 + 2 * tq);
            }
#pragma unroll
            for (int nt = 0; nt < 4; ++nt) {
                const int n0 = n_warp + nt * 8 + gq;
                const uint32_t b0 = lds32(WsT + n0 * LDH + k0 + 2 * tq);
                const uint32_t b1r = lds32(WsT + n0 * LDH + k0 + 8 + 2 * tq);
                mma16(acc[0][nt], a[0], b0, b1r);
                mma16(acc[1][nt], a[1], b0, b1r);
            }
        }
        __syncthreads();   // HB/QBh reads done; OS may overwrite

        // epilogue: relu(acc+b2) -> OS (aliases QB/HB), then coalesced STG.cs
#pragma unroll
        for (int nt = 0; nt < 4; ++nt) {
            const int n0 = n_warp + nt * 8 + tq * 2;
#pragma unroll
            for (int mt = 0; mt < 2; ++mt) {
                const int r0 = m_warp + mt * 16 + gq;
                *reinterpret_cast<float2*>(OS + r0 * LDX + n0) =
                    make_float2(fmaxf(acc[mt][nt][0] + b2v[nt][0], 0.f),
                                fmaxf(acc[mt][nt][1] + b2v[nt][1], 0.f));
                *reinterpret_cast<float2*>(OS + (r0 + 8) * LDX + n0) =
                    make_float2(fmaxf(acc[mt][nt][2] + b2v[nt][0], 0.f),
                                fmaxf(acc[mt][nt][3] + b2v[nt][1], 0.f));
            }
        }
        __syncthreads();
#pragma unroll
        for (int j = 0; j < 8; ++j) {
            const int row = j * 8 + wid;
            const float4 v = reinterpret_cast<const float4*>(OS + row * LDX)[lane];
            __stcs(reinterpret_cast<float4*>(out + (size_t)(eb + row) * 128) + lane, v);
        }
    }
}

extern "C" void kernel_launch(void* const* d_in, const int* in_sizes, int n_in,
                              void* d_out, int out_size) {
    const float* node_emb   = (const float*)d_in[0];
    const int*   edge_index = (const int*)d_in[1];   // int32
    const float* edge_sel   = (const float*)d_in[2];
    const float* W1         = (const float*)d_in[3];
    const float* b1         = (const float*)d_in[4];
    const float* W2         = (const float*)d_in[5];
    const float* b2         = (const float*)d_in[6];
    float*       out        = (float*)d_out;

    const int B  = 4;
    const int E  = in_sizes[2] / B;
    const int n_nodes = in_sizes[0] / (B * 128);
    const int BN = B * n_nodes;

    const int grid1 = (BN + 127) / 128;
    const int bpb   = E / 64;
    const int ntiles = B * bpb;

    int dev = 0, sms = 148;
    cudaGetDevice(&dev);
    cudaDeviceGetAttribute(&sms, cudaDevAttrMultiProcessorCount, dev);
    int grid2 = 2 * sms;
    if (grid2 > ntiles) grid2 = ntiles;

    const size_t smem1 = (size_t)(256 * LDH) * sizeof(half);
    const size_t smem2 = (size_t)E_SMB;
    cudaFuncSetAttribute(node_proj_kernel,
                         cudaFuncAttributeMaxDynamicSharedMemorySize, (int)smem1);
    cudaFuncSetAttribute(edge_kernel,
                         cudaFuncAttributeMaxDynamicSharedMemorySize, (int)smem2);

    node_proj_kernel<<<grid1, 256, smem1>>>(node_emb, W1, b1, BN);
    edge_kernel<<<grid2, 256, smem2>>>(edge_index, edge_sel, W1, W2, b2, out,
                                       E, bpb, n_nodes, ntiles);
}

// round 13
// speedup vs baseline: 2.9125x; 1.2406x over previous
#include <cuda_runtime.h>
#include <cuda_fp16.h>
#include <cstdint>
#include <cstddef>

// EdgeEncoder:
//   K1 (proj): P = f16(node_emb)@f16(W1a)+b1 ; Q = f16(node_emb)@f16(W1b)  [fp32 accum, P/Q fp16]
//   K2 (edge): 2 CTAs/SM persistent, software-pipelined:
//       Q(t+1) cp.async double-buffered, P(t+1) -> regs after combine(t),
//       H = f16(relu(P+Q+sel*w1c)); out = relu(H@f16(W2)+b2) direct STG.cs (full-sector).
// fp16 mma m16n8k16. edge_index is int32.

#define LDX 132
#define LDH 136    // fp16 padded row stride (halves)

#define MAXROWS 401408
__device__ half P_buf[(size_t)MAXROWS * 128];
__device__ half Q_buf[(size_t)MAXROWS * 128];

__device__ __forceinline__ uint32_t pack2(float a, float b) {
    half2 h = __floats2half2_rn(a, b);
    return *reinterpret_cast<uint32_t*>(&h);
}
__device__ __forceinline__ float2 unpack2(uint32_t u) {
    return __half22float2(*reinterpret_cast<half2*>(&u));
}
__device__ __forceinline__ uint32_t smem_u32(const void* p) {
    uint32_t a;
    asm("{ .reg .u64 t; cvta.to.shared.u64 t, %1; cvt.u32.u64 %0, t; }" : "=r"(a) : "l"(p));
    return a;
}
__device__ __forceinline__ void cp16(uint32_t dst, const void* src) {
    asm volatile("cp.async.cg.shared.global [%0], [%1], 16;" :: "r"(dst), "l"(src));
}
#define CP_COMMIT() asm volatile("cp.async.commit_group;" ::: "memory")
#define CP_WAIT1()  asm volatile("cp.async.wait_group 1;" ::: "memory")
#define CP_WAIT0()  asm volatile("cp.async.wait_group 0;" ::: "memory")

__device__ __forceinline__ void mma16(float c[4], const uint32_t a[4], uint32_t b0, uint32_t b1) {
    asm("mma.sync.aligned.m16n8k16.row.col.f32.f16.f16.f32 "
        "{%0,%1,%2,%3}, {%4,%5,%6,%7}, {%8,%9}, {%0,%1,%2,%3};"
        : "+f"(c[0]), "+f"(c[1]), "+f"(c[2]), "+f"(c[3])
        : "r"(a[0]), "r"(a[1]), "r"(a[2]), "r"(a[3]), "r"(b0), "r"(b1));
}
__device__ __forceinline__ uint32_t lds32(const half* p) {
    return *reinterpret_cast<const uint32_t*>(p);
}

// W[128k x 128n] fp32 row-major -> WsT[n][k] fp16, LDH stride.
__device__ __forceinline__ void load_wT(half* __restrict__ WsT,
                                        const float* __restrict__ src, int tid) {
    const int n = tid & 127, kh = tid >> 7;
#pragma unroll
    for (int g = 0; g < 8; ++g) {
        const int kb = kh * 64 + g * 8;
        uint4 u;
        u.x = pack2(src[(kb + 0) * 128 + n], src[(kb + 1) * 128 + n]);
        u.y = pack2(src[(kb + 2) * 128 + n], src[(kb + 3) * 128 + n]);
        u.z = pack2(src[(kb + 4) * 128 + n], src[(kb + 5) * 128 + n]);
        u.w = pack2(src[(kb + 6) * 128 + n], src[(kb + 7) * 128 + n]);
        *reinterpret_cast<uint4*>(WsT + n * LDH + kb) = u;
    }
}

// ================= Kernel 1: node projections (unchanged from R12) ==========
__global__ void __launch_bounds__(256, 2) node_proj_kernel(
    const float* __restrict__ node_emb,
    const float* __restrict__ W1,
    const float* __restrict__ b1,
    int BN)
{
    extern __shared__ char smc[];
    half* XsH  = reinterpret_cast<half*>(smc);
    half* WsT  = reinterpret_cast<half*>(smc) + 128 * LDH;

    const int tid  = threadIdx.x;
    const int wid  = tid >> 5;
    const int lane = tid & 31;
    const int gq   = lane >> 2;
    const int tq   = lane & 3;
    const int m_warp = (wid & 1) * 64;
    const int n_warp = (wid >> 1) * 32;
    const int gbase = blockIdx.x * 128;

    float b1v[4][2];
#pragma unroll
    for (int nt = 0; nt < 4; ++nt) {
        const int n0 = n_warp + nt * 8 + tq * 2;
        b1v[nt][0] = b1[n0];
        b1v[nt][1] = b1[n0 + 1];
    }

    {
        const int row = tid >> 1, h = tid & 1;
        int g = gbase + row;
        if (g >= BN) g = BN - 1;
        const float4* src = reinterpret_cast<const float4*>(node_emb + (size_t)g * 128 + h * 64);
        half* xrow = XsH + row * LDH + h * 64;
#pragma unroll
        for (int i = 0; i < 16; ++i) {
            const float4 v = src[i];
            *reinterpret_cast<uint2*>(xrow + i * 4) = make_uint2(pack2(v.x, v.y), pack2(v.z, v.w));
        }
    }
    load_wT(WsT, W1, tid);                 // W1a^T
    __syncthreads();

    float acc[4][4][4];
#pragma unroll
    for (int mt = 0; mt < 4; ++mt)
#pragma unroll
        for (int nt = 0; nt < 4; ++nt)
#pragma unroll
            for (int i = 0; i < 4; ++i) acc[mt][nt][i] = 0.f;

#pragma unroll
    for (int ks = 0; ks < 8; ++ks) {
        const int k0 = ks * 16;
        uint32_t a[4][4];
#pragma unroll
        for (int mt = 0; mt < 4; ++mt) {
            const int r0 = m_warp + mt * 16 + gq;
            a[mt][0] = lds32(XsH + r0 * LDH + k0 + 2 * tq);
            a[mt][1] = lds32(XsH + (r0 + 8) * LDH + k0 + 2 * tq);
            a[mt][2] = lds32(XsH + r0 * LDH + k0 + 8 + 2 * tq);
            a[mt][3] = lds32(XsH + (r0 + 8) * LDH + k0 + 8 + 2 * tq);
        }
#pragma unroll
        for (int nt = 0; nt < 4; ++nt) {
            const int n0 = n_warp + nt * 8 + gq;
            const uint32_t b0 = lds32(WsT + n0 * LDH + k0 + 2 * tq);
            const uint32_t b1r = lds32(WsT + n0 * LDH + k0 + 8 + 2 * tq);
#pragma unroll
            for (int mt = 0; mt < 4; ++mt) mma16(acc[mt][nt], a[mt], b0, b1r);
        }
    }

#pragma unroll
    for (int nt = 0; nt < 4; ++nt) {
        const int n0 = n_warp + nt * 8 + tq * 2;
#pragma unroll
        for (int mt = 0; mt < 4; ++mt) {
            const int r0 = gbase + m_warp + mt * 16 + gq;
            if (r0 < BN)
                *reinterpret_cast<uint32_t*>(P_buf + (size_t)r0 * 128 + n0) =
                    pack2(acc[mt][nt][0] + b1v[nt][0], acc[mt][nt][1] + b1v[nt][1]);
            if (r0 + 8 < BN)
                *reinterpret_cast<uint32_t*>(P_buf + (size_t)(r0 + 8) * 128 + n0) =
                    pack2(acc[mt][nt][2] + b1v[nt][0], acc[mt][nt][3] + b1v[nt][1]);
            acc[mt][nt][0] = acc[mt][nt][1] = acc[mt][nt][2] = acc[mt][nt][3] = 0.f;
        }
    }
    __syncthreads();
    load_wT(WsT, W1 + 128 * 128, tid);     // W1b^T
    __syncthreads();

#pragma unroll
    for (int ks = 0; ks < 8; ++ks) {
        const int k0 = ks * 16;
        uint32_t a[4][4];
#pragma unroll
        for (int mt = 0; mt < 4; ++mt) {
            const int r0 = m_warp + mt * 16 + gq;
            a[mt][0] = lds32(XsH + r0 * LDH + k0 + 2 * tq);
            a[mt][1] = lds32(XsH + (r0 + 8) * LDH + k0 + 2 * tq);
            a[mt][2] = lds32(XsH + r0 * LDH + k0 + 8 + 2 * tq);
            a[mt][3] = lds32(XsH + (r0 + 8) * LDH + k0 + 8 + 2 * tq);
        }
#pragma unroll
        for (int nt = 0; nt < 4; ++nt) {
            const int n0 = n_warp + nt * 8 + gq;
            const uint32_t b0 = lds32(WsT + n0 * LDH + k0 + 2 * tq);
            const uint32_t b1r = lds32(WsT + n0 * LDH + k0 + 8 + 2 * tq);
#pragma unroll
            for (int mt = 0; mt < 4; ++mt) mma16(acc[mt][nt], a[mt], b0, b1r);
        }
    }
#pragma unroll
    for (int nt = 0; nt < 4; ++nt) {
        const int n0 = n_warp + nt * 8 + tq * 2;
#pragma unroll
        for (int mt = 0; mt < 4; ++mt) {
            const int r0 = gbase + m_warp + mt * 16 + gq;
            if (r0 < BN)
                *reinterpret_cast<uint32_t*>(Q_buf + (size_t)r0 * 128 + n0) =
                    pack2(acc[mt][nt][0], acc[mt][nt][1]);
            if (r0 + 8 < BN)
                *reinterpret_cast<uint32_t*>(Q_buf + (size_t)(r0 + 8) * 128 + n0) =
                    pack2(acc[mt][nt][2], acc[mt][nt][3]);
        }
    }
}

// ================= Kernel 2: edge, software-pipelined (2 CTAs/SM) =================
// smem byte offsets
#define E_WT   0                          // WsT: 128*LDH*2 = 34816
#define E_QB   34816                      // QB fp16 x2 stages: 2*64*128*2 = 32768
#define E_HB   67584                      // HB fp16 padded: 64*LDH*2 = 17408
#define E_SEL  84992                      // float[2][64] = 512
#define E_IDX  85504                      // int2[2][64] = 1024
#define E_SMB  86528

__global__ void __launch_bounds__(256, 2) edge_kernel(
    const int* __restrict__ edge_index,
    const float* __restrict__ edge_sel,
    const float* __restrict__ W1,
    const float* __restrict__ W2,
    const float* __restrict__ b2,
    float* __restrict__ out,
    int E, int bpb, int n_nodes, int ntiles)
{
    extern __shared__ char smc[];
    half*  WsT  = reinterpret_cast<half*>(smc + E_WT);
    half*  QB0  = reinterpret_cast<half*>(smc + E_QB);   // stage stride 8192 halves
    half*  HB   = reinterpret_cast<half*>(smc + E_HB);
    float* sels = reinterpret_cast<float*>(smc + E_SEL);
    int2*  idxs = reinterpret_cast<int2*>(smc + E_IDX);
    const uint32_t qb_base = smem_u32(smc) + E_QB;

    const int tid  = threadIdx.x;
    const int wid  = tid >> 5;
    const int lane = tid & 31;
    const int gq   = lane >> 2;
    const int tq   = lane & 3;
    const int m_warp = (wid & 1) * 32;
    const int n_warp = (wid >> 1) * 32;
    const int rsub  = lane >> 4;           // 0/1
    const int chunk = lane & 15;           // 16B chunk

    float w1cv8[8];
#pragma unroll
    for (int j = 0; j < 8; ++j) w1cv8[j] = W1[256 * 128 + chunk * 8 + j];

    float b2v[4][2];
#pragma unroll
    for (int nt = 0; nt < 4; ++nt) {
        const int n0 = n_warp + nt * 8 + tq * 2;
        b2v[nt][0] = b2[n0];
        b2v[nt][1] = b2[n0 + 1];
    }

    load_wT(WsT, W2, tid);   // one-time

    const int stride = gridDim.x;
    const int t0 = blockIdx.x;
    auto ebase = [&](int t) -> long long {
        const int b = t / bpb;
        return (long long)b * E + (long long)(t - b * bpb) * 64;
    };

    // ---- prologue: idx(t0) -> idxs[0]; idx(t1) -> regs; issue Q(t0), P(t0) ----
    int2  idx_n;
    float sel_n;
    {
        const long long eb0 = ebase(t0);
        int t1 = t0 + stride; if (t1 >= ntiles) t1 = t0;
        const long long eb1 = ebase(t1);
        if (tid < 64) {
            idxs[tid] = reinterpret_cast<const int2*>(edge_index)[eb0 + tid];
            sels[tid] = edge_sel[eb0 + tid];
            idx_n = reinterpret_cast<const int2*>(edge_index)[eb1 + tid];
            sel_n = edge_sel[eb1 + tid];
        }
    }
    __syncthreads();

    uint4 pv[4];
    {
        const size_t rowbase = (size_t)(t0 / bpb) * n_nodes;
#pragma unroll
        for (int r = 0; r < 4; ++r) {
            const int row = wid * 8 + 2 * r + rsub;
            int iv = idxs[row].y;
            iv = min(max(iv, 0), n_nodes - 1);
            cp16(qb_base + (uint32_t)(row * 256 + chunk * 16),
                 Q_buf + (rowbase + iv) * 128 + chunk * 8);
        }
        CP_COMMIT();
#pragma unroll
        for (int r = 0; r < 4; ++r) {
            const int row = wid * 8 + 2 * r + rsub;
            int iu = idxs[row].x;
            iu = min(max(iu, 0), n_nodes - 1);
            pv[r] = __ldcg(reinterpret_cast<const uint4*>(
                P_buf + (rowbase + iu) * 128 + chunk * 8));
        }
    }

    int i = 0;
    for (int t = t0; t < ntiles; t += stride, ++i) {
        const int cur = i & 1, nxt = cur ^ 1;
        const long long eb = ebase(t);
        int t1 = t + stride; if (t1 >= ntiles) t1 = t;
        const size_t rowbase1 = (size_t)(t1 / bpb) * n_nodes;

        // stage idx(t+1) to smem, prefetch idx(t+2) to regs
        if (tid < 64) {
            idxs[nxt * 64 + tid] = idx_n;
            sels[nxt * 64 + tid] = sel_n;
            int t2 = t + 2 * stride; if (t2 >= ntiles) t2 = t;
            const long long eb2 = ebase(t2);
            idx_n = reinterpret_cast<const int2*>(edge_index)[eb2 + tid];
            sel_n = edge_sel[eb2 + tid];
        }
        __syncthreads();   // s1: idxs[nxt] visible; also HB WAR vs prev GEMM

        // issue Q(t+1) -> QB[nxt]
#pragma unroll
        for (int r = 0; r < 4; ++r) {
            const int row = wid * 8 + 2 * r + rsub;
            int iv = idxs[nxt * 64 + row].y;
            iv = min(max(iv, 0), n_nodes - 1);
            cp16(qb_base + (uint32_t)(nxt * 16384 + row * 256 + chunk * 16),
                 Q_buf + (rowbase1 + iv) * 128 + chunk * 8);
        }
        CP_COMMIT();

        CP_WAIT1();        // Q(t) arrived (self-issued bytes, same thread consumes)

        // combine(t): H = f16(relu(P + Q + sel*w1c)) -> HB
        const half* QBc = QB0 + cur * 8192;
#pragma unroll
        for (int r = 0; r < 4; ++r) {
            const int row = wid * 8 + 2 * r + rsub;
            const uint4 q = *reinterpret_cast<const uint4*>(QBc + row * 128 + chunk * 8);
            const uint4 p = pv[r];
            const float s = sels[cur * 64 + row];
            const float2 p0 = unpack2(p.x), p1 = unpack2(p.y), p2 = unpack2(p.z), p3 = unpack2(p.w);
            const float2 q0 = unpack2(q.x), q1 = unpack2(q.y), q2 = unpack2(q.z), q3 = unpack2(q.w);
            uint4 h;
            h.x = pack2(fmaxf(p0.x + q0.x + s * w1cv8[0], 0.f),
                        fmaxf(p0.y + q0.y + s * w1cv8[1], 0.f));
            h.y = pack2(fmaxf(p1.x + q1.x + s * w1cv8[2], 0.f),
                        fmaxf(p1.y + q1.y + s * w1cv8[3], 0.f));
            h.z = pack2(fmaxf(p2.x + q2.x + s * w1cv8[4], 0.f),
                        fmaxf(p2.y + q2.y + s * w1cv8[5], 0.f));
            h.w = pack2(fmaxf(p3.x + q3.x + s * w1cv8[6], 0.f),
                        fmaxf(p3.y + q3.y + s * w1cv8[7], 0.f));
            *reinterpret_cast<uint4*>(HB + row * LDH + chunk * 8) = h;
        }

        // issue P(t+1) -> pv (pv(t) consumed above)
#pragma unroll
        for (int r = 0; r < 4; ++r) {
            const int row = wid * 8 + 2 * r + rsub;
            int iu = idxs[nxt * 64 + row].x;
            iu = min(max(iu, 0), n_nodes - 1);
            pv[r] = __ldcg(reinterpret_cast<const uint4*>(
                P_buf + (rowbase1 + iu) * 128 + chunk * 8));
        }
        __syncthreads();   // s2: HB visible for GEMM

        // GEMM2: 64x128x128 fp16, A = HB, B = WsT
        float acc[2][4][4];
#pragma unroll
        for (int mt = 0; mt < 2; ++mt)
#pragma unroll
            for (int nt = 0; nt < 4; ++nt)
#pragma unroll
                for (int k = 0; k < 4; ++k) acc[mt][nt][k] = 0.f;

#pragma unroll
        for (int ks = 0; ks < 8; ++ks) {
            const int k0 = ks * 16;
            uint32_t a[2][4];
#pragma unroll
            for (int mt = 0; mt < 2; ++mt) {
                const int r0 = m_warp + mt * 16 + gq;
                a[mt][0] = lds32(HB + r0 * LDH + k0 + 2 * tq);
                a[mt][1] = lds32(HB + (r0 + 8) * LDH + k0 + 2 * tq);
                a[mt][2] = lds32(HB + r0 * LDH + k0 + 8 + 2 * tq);
                a[mt][3] = lds32(HB + (r0 + 8) * LDH + k0 + 8 + 2 * tq);
            }
#pragma unroll
            for (int nt = 0; nt < 4; ++nt) {
                const int n0 = n_warp + nt * 8 + gq;
                const uint32_t b0 = lds32(WsT + n0 * LDH + k0 + 2 * tq);
                const uint32_t b1r = lds32(WsT + n0 * LDH + k0 + 8 + 2 * tq);
                mma16(acc[0][nt], a[0], b0, b1r);
                mma16(acc[1][nt], a[1], b0, b1r);
            }
        }

        // epilogue: direct full-sector STG.cs (4 tq-lanes cover one 32B sector per row)
#pragma unroll
        for (int nt = 0; nt < 4; ++nt) {
            const int n0 = n_warp + nt * 8 + tq * 2;
#pragma unroll
            for (int mt = 0; mt < 2; ++mt) {
                const int r0 = m_warp + mt * 16 + gq;
                float2 o0 = make_float2(fmaxf(acc[mt][nt][0] + b2v[nt][0], 0.f),
                                        fmaxf(acc[mt][nt][1] + b2v[nt][1], 0.f));
                float2 o1 = make_float2(fmaxf(acc[mt][nt][2] + b2v[nt][0], 0.f),
                                        fmaxf(acc[mt][nt][3] + b2v[nt][1], 0.f));
                __stcs(reinterpret_cast<float2*>(out + (size_t)(eb + r0) * 128 + n0), o0);
                __stcs(reinterpret_cast<float2*>(out + (size_t)(eb + r0 + 8) * 128 + n0), o1);
            }
        }
    }
    CP_WAIT0();
}

extern "C" void kernel_launch(void* const* d_in, const int* in_sizes, int n_in,
                              void* d_out, int out_size) {
    const float* node_emb   = (const float*)d_in[0];
    const int*   edge_index = (const int*)d_in[1];   // int32
    const float* edge_sel   = (const float*)d_in[2];
    const float* W1         = (const float*)d_in[3];
    const float* b1         = (const float*)d_in[4];
    const float* W2         = (const float*)d_in[5];
    const float* b2         = (const float*)d_in[6];
    float*       out        = (float*)d_out;

    const int B  = 4;
    const int E  = in_sizes[2] / B;
    const int n_nodes = in_sizes[0] / (B * 128);
    const int BN = B * n_nodes;

    const int grid1 = (BN + 127) / 128;
    const int bpb   = E / 64;
    const int ntiles = B * bpb;

    int dev = 0, sms = 148;
    cudaGetDevice(&dev);
    cudaDeviceGetAttribute(&sms, cudaDevAttrMultiProcessorCount, dev);
    int grid2 = 2 * sms;
    if (grid2 > ntiles) grid2 = ntiles;

    const size_t smem1 = (size_t)(256 * LDH) * sizeof(half);
    const size_t smem2 = (size_t)E_SMB;
    cudaFuncSetAttribute(node_proj_kernel,
                         cudaFuncAttributeMaxDynamicSharedMemorySize, (int)smem1);
    cudaFuncSetAttribute(edge_kernel,
                         cudaFuncAttributeMaxDynamicSharedMemorySize, (int)smem2);

    node_proj_kernel<<<grid1, 256, smem1>>>(node_emb, W1, b1, BN);
    edge_kernel<<<grid2, 256, smem2>>>(edge_index, edge_sel, W1, W2, b2, out,
                                       E, bpb, n_nodes, ntiles);
}

// round 14
// speedup vs baseline: 3.0524x; 1.0480x over previous
#include <cuda_runtime.h>
#include <cuda_fp16.h>
#include <cstdint>
#include <cstddef>

// EdgeEncoder:
//   K1 (proj): P = f16(node_emb)@f16(W1a)+b1 ; Q = f16(node_emb)@f16(W1b)  [fp32 accum, P/Q fp16]
//   K2 (edge): 2 CTAs/SM persistent, pipelined; TRANSPOSED GEMM2:
//       out^T = W2^T @ H^T with A = W2^T STATIC IN REGISTERS (64 regs/thread, loaded once),
//       B = H from smem. P,Q both cp.async double-buffered; H = f16(relu(P+Q+sel*w1c)).
// fp16 mma m16n8k16. edge_index is int32.

#define LDH 136    // fp16 padded row stride (halves)

#define MAXROWS 401408
__device__ half P_buf[(size_t)MAXROWS * 128];
__device__ half Q_buf[(size_t)MAXROWS * 128];

__device__ __forceinline__ uint32_t pack2(float a, float b) {
    half2 h = __floats2half2_rn(a, b);
    return *reinterpret_cast<uint32_t*>(&h);
}
__device__ __forceinline__ float2 unpack2(uint32_t u) {
    return __half22float2(*reinterpret_cast<half2*>(&u));
}
__device__ __forceinline__ uint32_t smem_u32(const void* p) {
    uint32_t a;
    asm("{ .reg .u64 t; cvta.to.shared.u64 t, %1; cvt.u32.u64 %0, t; }" : "=r"(a) : "l"(p));
    return a;
}
__device__ __forceinline__ void cp16(uint32_t dst, const void* src) {
    asm volatile("cp.async.cg.shared.global [%0], [%1], 16;" :: "r"(dst), "l"(src));
}
#define CP_COMMIT() asm volatile("cp.async.commit_group;" ::: "memory")
#define CP_WAIT1()  asm volatile("cp.async.wait_group 1;" ::: "memory")
#define CP_WAIT0()  asm volatile("cp.async.wait_group 0;" ::: "memory")

__device__ __forceinline__ void mma16(float c[4], const uint32_t a[4], uint32_t b0, uint32_t b1) {
    asm("mma.sync.aligned.m16n8k16.row.col.f32.f16.f16.f32 "
        "{%0,%1,%2,%3}, {%4,%5,%6,%7}, {%8,%9}, {%0,%1,%2,%3};"
        : "+f"(c[0]), "+f"(c[1]), "+f"(c[2]), "+f"(c[3])
        : "r"(a[0]), "r"(a[1]), "r"(a[2]), "r"(a[3]), "r"(b0), "r"(b1));
}
__device__ __forceinline__ uint32_t lds32(const half* p) {
    return *reinterpret_cast<const uint32_t*>(p);
}

// W[128k x 128n] fp32 row-major -> WsT[n][k] fp16, LDH stride. (proj only)
__device__ __forceinline__ void load_wT(half* __restrict__ WsT,
                                        const float* __restrict__ src, int tid) {
    const int n = tid & 127, kh = tid >> 7;
#pragma unroll
    for (int g = 0; g < 8; ++g) {
        const int kb = kh * 64 + g * 8;
        uint4 u;
        u.x = pack2(src[(kb + 0) * 128 + n], src[(kb + 1) * 128 + n]);
        u.y = pack2(src[(kb + 2) * 128 + n], src[(kb + 3) * 128 + n]);
        u.z = pack2(src[(kb + 4) * 128 + n], src[(kb + 5) * 128 + n]);
        u.w = pack2(src[(kb + 6) * 128 + n], src[(kb + 7) * 128 + n]);
        *reinterpret_cast<uint4*>(WsT + n * LDH + kb) = u;
    }
}

// ================= Kernel 1: node projections (unchanged from R13) ==========
__global__ void __launch_bounds__(256, 2) node_proj_kernel(
    const float* __restrict__ node_emb,
    const float* __restrict__ W1,
    const float* __restrict__ b1,
    int BN)
{
    extern __shared__ char smc[];
    half* XsH  = reinterpret_cast<half*>(smc);
    half* WsT  = reinterpret_cast<half*>(smc) + 128 * LDH;

    const int tid  = threadIdx.x;
    const int wid  = tid >> 5;
    const int lane = tid & 31;
    const int gq   = lane >> 2;
    const int tq   = lane & 3;
    const int m_warp = (wid & 1) * 64;
    const int n_warp = (wid >> 1) * 32;
    const int gbase = blockIdx.x * 128;

    float b1v[4][2];
#pragma unroll
    for (int nt = 0; nt < 4; ++nt) {
        const int n0 = n_warp + nt * 8 + tq * 2;
        b1v[nt][0] = b1[n0];
        b1v[nt][1] = b1[n0 + 1];
    }

    {
        const int row = tid >> 1, h = tid & 1;
        int g = gbase + row;
        if (g >= BN) g = BN - 1;
        const float4* src = reinterpret_cast<const float4*>(node_emb + (size_t)g * 128 + h * 64);
        half* xrow = XsH + row * LDH + h * 64;
#pragma unroll
        for (int i = 0; i < 16; ++i) {
            const float4 v = src[i];
            *reinterpret_cast<uint2*>(xrow + i * 4) = make_uint2(pack2(v.x, v.y), pack2(v.z, v.w));
        }
    }
    load_wT(WsT, W1, tid);                 // W1a^T
    __syncthreads();

    float acc[4][4][4];
#pragma unroll
    for (int mt = 0; mt < 4; ++mt)
#pragma unroll
        for (int nt = 0; nt < 4; ++nt)
#pragma unroll
            for (int i = 0; i < 4; ++i) acc[mt][nt][i] = 0.f;

#pragma unroll
    for (int ks = 0; ks < 8; ++ks) {
        const int k0 = ks * 16;
        uint32_t a[4][4];
#pragma unroll
        for (int mt = 0; mt < 4; ++mt) {
            const int r0 = m_warp + mt * 16 + gq;
            a[mt][0] = lds32(XsH + r0 * LDH + k0 + 2 * tq);
            a[mt][1] = lds32(XsH + (r0 + 8) * LDH + k0 + 2 * tq);
            a[mt][2] = lds32(XsH + r0 * LDH + k0 + 8 + 2 * tq);
            a[mt][3] = lds32(XsH + (r0 + 8) * LDH + k0 + 8 + 2 * tq);
        }
#pragma unroll
        for (int nt = 0; nt < 4; ++nt) {
            const int n0 = n_warp + nt * 8 + gq;
            const uint32_t b0 = lds32(WsT + n0 * LDH + k0 + 2 * tq);
            const uint32_t b1r = lds32(WsT + n0 * LDH + k0 + 8 + 2 * tq);
#pragma unroll
            for (int mt = 0; mt < 4; ++mt) mma16(acc[mt][nt], a[mt], b0, b1r);
        }
    }

#pragma unroll
    for (int nt = 0; nt < 4; ++nt) {
        const int n0 = n_warp + nt * 8 + tq * 2;
#pragma unroll
        for (int mt = 0; mt < 4; ++mt) {
            const int r0 = gbase + m_warp + mt * 16 + gq;
            if (r0 < BN)
                *reinterpret_cast<uint32_t*>(P_buf + (size_t)r0 * 128 + n0) =
                    pack2(acc[mt][nt][0] + b1v[nt][0], acc[mt][nt][1] + b1v[nt][1]);
            if (r0 + 8 < BN)
                *reinterpret_cast<uint32_t*>(P_buf + (size_t)(r0 + 8) * 128 + n0) =
                    pack2(acc[mt][nt][2] + b1v[nt][0], acc[mt][nt][3] + b1v[nt][1]);
            acc[mt][nt][0] = acc[mt][nt][1] = acc[mt][nt][2] = acc[mt][nt][3] = 0.f;
        }
    }
    __syncthreads();
    load_wT(WsT, W1 + 128 * 128, tid);     // W1b^T
    __syncthreads();

#pragma unroll
    for (int ks = 0; ks < 8; ++ks) {
        const int k0 = ks * 16;
        uint32_t a[4][4];
#pragma unroll
        for (int mt = 0; mt < 4; ++mt) {
            const int r0 = m_warp + mt * 16 + gq;
            a[mt][0] = lds32(XsH + r0 * LDH + k0 + 2 * tq);
            a[mt][1] = lds32(XsH + (r0 + 8) * LDH + k0 + 2 * tq);
            a[mt][2] = lds32(XsH + r0 * LDH + k0 + 8 + 2 * tq);
            a[mt][3] = lds32(XsH + (r0 + 8) * LDH + k0 + 8 + 2 * tq);
        }
#pragma unroll
        for (int nt = 0; nt < 4; ++nt) {
            const int n0 = n_warp + nt * 8 + gq;
            const uint32_t b0 = lds32(WsT + n0 * LDH + k0 + 2 * tq);
            const uint32_t b1r = lds32(WsT + n0 * LDH + k0 + 8 + 2 * tq);
#pragma unroll
            for (int mt = 0; mt < 4; ++mt) mma16(acc[mt][nt], a[mt], b0, b1r);
        }
    }
#pragma unroll
    for (int nt = 0; nt < 4; ++nt) {
        const int n0 = n_warp + nt * 8 + tq * 2;
#pragma unroll
        for (int mt = 0; mt < 4; ++mt) {
            const int r0 = gbase + m_warp + mt * 16 + gq;
            if (r0 < BN)
                *reinterpret_cast<uint32_t*>(Q_buf + (size_t)r0 * 128 + n0) =
                    pack2(acc[mt][nt][0], acc[mt][nt][1]);
            if (r0 + 8 < BN)
                *reinterpret_cast<uint32_t*>(Q_buf + (size_t)(r0 + 8) * 128 + n0) =
                    pack2(acc[mt][nt][2], acc[mt][nt][3]);
        }
    }
}

// ================= Kernel 2: edge, transposed GEMM2, W2-in-regs =================
// smem byte offsets
#define E_QB   0                          // Q fp16 x2 stages: 2*64*128*2 = 32768
#define E_PB   32768                      // P fp16 x2 stages: 32768
#define E_HB   65536                      // HB fp16 padded: 64*LDH*2 = 17408
#define E_SEL  82944                      // float[2][64] = 512
#define E_IDX  83456                      // int2[2][64] = 1024
#define E_W1C  84480                      // float[128] = 512
#define E_SMB  84992

__global__ void __launch_bounds__(256, 2) edge_kernel(
    const int* __restrict__ edge_index,
    const float* __restrict__ edge_sel,
    const float* __restrict__ W1,
    const float* __restrict__ W2,
    const float* __restrict__ b2,
    float* __restrict__ out,
    int E, int bpb, int n_nodes, int ntiles)
{
    extern __shared__ char smc[];
    half*  QB0  = reinterpret_cast<half*>(smc + E_QB);   // stage stride 8192 halves
    half*  PB0  = reinterpret_cast<half*>(smc + E_PB);
    half*  HB   = reinterpret_cast<half*>(smc + E_HB);
    float* sels = reinterpret_cast<float*>(smc + E_SEL);
    int2*  idxs = reinterpret_cast<int2*>(smc + E_IDX);
    float* w1cs = reinterpret_cast<float*>(smc + E_W1C);
    const uint32_t qb_base = smem_u32(smc) + E_QB;
    const uint32_t pb_base = smem_u32(smc) + E_PB;

    const int tid  = threadIdx.x;
    const int wid  = tid >> 5;
    const int lane = tid & 31;
    const int gq   = lane >> 2;
    const int tq   = lane & 3;
    const int oc_warp = (wid & 3) * 32;    // 4 outcol-splits of 32
    const int e_warp  = (wid >> 2) * 32;   // 2 edge-splits of 32
    const int rsub  = lane >> 4;           // 0/1
    const int chunk = lane & 15;           // 16B chunk

    // ---- one-time: W2^T A-fragments into 64 static registers ----
    // a0=(oc=gq, k=2tq+{0,1}), a1=(oc+8), a2=(k+8), a3=(oc+8,k+8); A[oc][k]=W2[k*128+oc]
    uint32_t w2a[8][2][4];
#pragma unroll
    for (int ks = 0; ks < 8; ++ks)
#pragma unroll
        for (int mt = 0; mt < 2; ++mt) {
            const int oc = oc_warp + mt * 16 + gq;
            const int k0 = ks * 16 + 2 * tq;
            w2a[ks][mt][0] = pack2(W2[k0 * 128 + oc],       W2[(k0 + 1) * 128 + oc]);
            w2a[ks][mt][1] = pack2(W2[k0 * 128 + oc + 8],   W2[(k0 + 1) * 128 + oc + 8]);
            w2a[ks][mt][2] = pack2(W2[(k0 + 8) * 128 + oc], W2[(k0 + 9) * 128 + oc]);
            w2a[ks][mt][3] = pack2(W2[(k0 + 8) * 128 + oc + 8], W2[(k0 + 9) * 128 + oc + 8]);
        }

    // bias per outcol (c rows)
    float b2v[2][2];
#pragma unroll
    for (int mt = 0; mt < 2; ++mt) {
        b2v[mt][0] = b2[oc_warp + mt * 16 + gq];
        b2v[mt][1] = b2[oc_warp + mt * 16 + gq + 8];
    }

    const int stride = gridDim.x;
    const int t0 = blockIdx.x;
    auto ebase = [&](int t) -> long long {
        const int b = t / bpb;
        return (long long)b * E + (long long)(t - b * bpb) * 64;
    };

    // ---- prologue ----
    int2  idx_n;
    float sel_n;
    {
        const long long eb0 = ebase(t0);
        int t1 = t0 + stride; if (t1 >= ntiles) t1 = t0;
        const long long eb1 = ebase(t1);
        if (tid < 64) {
            idxs[tid] = reinterpret_cast<const int2*>(edge_index)[eb0 + tid];
            sels[tid] = edge_sel[eb0 + tid];
            idx_n = reinterpret_cast<const int2*>(edge_index)[eb1 + tid];
            sel_n = edge_sel[eb1 + tid];
        }
        if (tid < 128) w1cs[tid] = W1[256 * 128 + tid];
    }
    __syncthreads();

    // issue Q(t0), P(t0) as one group
    {
        const size_t rowbase = (size_t)(t0 / bpb) * n_nodes;
#pragma unroll
        for (int r = 0; r < 4; ++r) {
            const int row = wid * 8 + 2 * r + rsub;
            int iv = idxs[row].y;
            int iu = idxs[row].x;
            iv = min(max(iv, 0), n_nodes - 1);
            iu = min(max(iu, 0), n_nodes - 1);
            cp16(qb_base + (uint32_t)(row * 256 + chunk * 16),
                 Q_buf + (rowbase + iv) * 128 + chunk * 8);
            cp16(pb_base + (uint32_t)(row * 256 + chunk * 16),
                 P_buf + (rowbase + iu) * 128 + chunk * 8);
        }
        CP_COMMIT();
    }

    int i = 0;
    for (int t = t0; t < ntiles; t += stride, ++i) {
        const int cur = i & 1, nxt = cur ^ 1;
        const long long eb = ebase(t);
        int t1 = t + stride; if (t1 >= ntiles) t1 = t;
        const size_t rowbase1 = (size_t)(t1 / bpb) * n_nodes;

        // stage idx(t+1), prefetch idx(t+2)
        if (tid < 64) {
            idxs[nxt * 64 + tid] = idx_n;
            sels[nxt * 64 + tid] = sel_n;
            int t2 = t + 2 * stride; if (t2 >= ntiles) t2 = t;
            const long long eb2 = ebase(t2);
            idx_n = reinterpret_cast<const int2*>(edge_index)[eb2 + tid];
            sel_n = edge_sel[eb2 + tid];
        }
        __syncthreads();   // s1: idxs[nxt] visible; HB WAR vs prev GEMM

        // issue Q(t+1), P(t+1) -> stage nxt
#pragma unroll
        for (int r = 0; r < 4; ++r) {
            const int row = wid * 8 + 2 * r + rsub;
            int iv = idxs[nxt * 64 + row].y;
            int iu = idxs[nxt * 64 + row].x;
            iv = min(max(iv, 0), n_nodes - 1);
            iu = min(max(iu, 0), n_nodes - 1);
            cp16(qb_base + (uint32_t)(nxt * 16384 + row * 256 + chunk * 16),
                 Q_buf + (rowbase1 + iv) * 128 + chunk * 8);
            cp16(pb_base + (uint32_t)(nxt * 16384 + row * 256 + chunk * 16),
                 P_buf + (rowbase1 + iu) * 128 + chunk * 8);
        }
        CP_COMMIT();

        CP_WAIT1();        // stage cur arrived (self-issued bytes, same thread consumes)

        // combine(t): H = f16(relu(P + Q + sel*w1c)) -> HB
        {
            const half* QBc = QB0 + cur * 8192;
            const half* PBc = PB0 + cur * 8192;
            const float4 wa = reinterpret_cast<const float4*>(w1cs + chunk * 8)[0];
            const float4 wb = reinterpret_cast<const float4*>(w1cs + chunk * 8)[1];
#pragma unroll
            for (int r = 0; r < 4; ++r) {
                const int row = wid * 8 + 2 * r + rsub;
                const uint4 q = *reinterpret_cast<const uint4*>(QBc + row * 128 + chunk * 8);
                const uint4 p = *reinterpret_cast<const uint4*>(PBc + row * 128 + chunk * 8);
                const float s = sels[cur * 64 + row];
                const float2 p0 = unpack2(p.x), p1 = unpack2(p.y), p2 = unpack2(p.z), p3 = unpack2(p.w);
                const float2 q0 = unpack2(q.x), q1 = unpack2(q.y), q2 = unpack2(q.z), q3 = unpack2(q.w);
                uint4 h;
                h.x = pack2(fmaxf(p0.x + q0.x + s * wa.x, 0.f),
                            fmaxf(p0.y + q0.y + s * wa.y, 0.f));
                h.y = pack2(fmaxf(p1.x + q1.x + s * wa.z, 0.f),
                            fmaxf(p1.y + q1.y + s * wa.w, 0.f));
                h.z = pack2(fmaxf(p2.x + q2.x + s * wb.x, 0.f),
                            fmaxf(p2.y + q2.y + s * wb.y, 0.f));
                h.w = pack2(fmaxf(p3.x + q3.x + s * wb.z, 0.f),
                            fmaxf(p3.y + q3.y + s * wb.w, 0.f));
                *reinterpret_cast<uint4*>(HB + row * LDH + chunk * 8) = h;
            }
        }
        __syncthreads();   // s2: HB visible for GEMM

        // GEMM2 (transposed): D' = W2^T @ H^T ; A = w2a regs, B = HB
        float acc[2][4][4];
#pragma unroll
        for (int mt = 0; mt < 2; ++mt)
#pragma unroll
            for (int nt = 0; nt < 4; ++nt)
#pragma unroll
                for (int k = 0; k < 4; ++k) acc[mt][nt][k] = 0.f;

#pragma unroll
        for (int ks = 0; ks < 8; ++ks) {
            const int k0 = ks * 16;
#pragma unroll
            for (int nt = 0; nt < 4; ++nt) {
                const int e = e_warp + nt * 8 + gq;
                const uint32_t b0 = lds32(HB + e * LDH + k0 + 2 * tq);
                const uint32_t b1r = lds32(HB + e * LDH + k0 + 8 + 2 * tq);
                mma16(acc[0][nt], w2a[ks][0], b0, b1r);
                mma16(acc[1][nt], w2a[ks][1], b0, b1r);
            }
        }

        // epilogue: out[(eb+e)*128 + oc] = relu(acc + b2[oc]) ; full-sector STG.32
#pragma unroll
        for (int nt = 0; nt < 4; ++nt) {
            const long long e0 = eb + e_warp + nt * 8 + 2 * tq;
#pragma unroll
            for (int mt = 0; mt < 2; ++mt) {
                const int oc = oc_warp + mt * 16 + gq;
                __stcs(out + (size_t)e0 * 128 + oc,
                       fmaxf(acc[mt][nt][0] + b2v[mt][0], 0.f));
                __stcs(out + (size_t)(e0 + 1) * 128 + oc,
                       fmaxf(acc[mt][nt][1] + b2v[mt][0], 0.f));
                __stcs(out + (size_t)e0 * 128 + oc + 8,
                       fmaxf(acc[mt][nt][2] + b2v[mt][1], 0.f));
                __stcs(out + (size_t)(e0 + 1) * 128 + oc + 8,
                       fmaxf(acc[mt][nt][3] + b2v[mt][1], 0.f));
            }
        }
    }
    CP_WAIT0();
}

extern "C" void kernel_launch(void* const* d_in, const int* in_sizes, int n_in,
                              void* d_out, int out_size) {
    const float* node_emb   = (const float*)d_in[0];
    const int*   edge_index = (const int*)d_in[1];   // int32
    const float* edge_sel   = (const float*)d_in[2];
    const float* W1         = (const float*)d_in[3];
    const float* b1         = (const float*)d_in[4];
    const float* W2         = (const float*)d_in[5];
    const float* b2         = (const float*)d_in[6];
    float*       out        = (float*)d_out;

    const int B  = 4;
    const int E  = in_sizes[2] / B;
    const int n_nodes = in_sizes[0] / (B * 128);
    const int BN = B * n_nodes;

    const int grid1 = (BN + 127) / 128;
    const int bpb   = E / 64;
    const int ntiles = B * bpb;

    int dev = 0, sms = 148;
    cudaGetDevice(&dev);
    cudaDeviceGetAttribute(&sms, cudaDevAttrMultiProcessorCount, dev);
    int grid2 = 2 * sms;
    if (grid2 > ntiles) grid2 = ntiles;

    const size_t smem1 = (size_t)(256 * LDH) * sizeof(half);
    const size_t smem2 = (size_t)E_SMB;
    cudaFuncSetAttribute(node_proj_kernel,
                         cudaFuncAttributeMaxDynamicSharedMemorySize, (int)smem1);
    cudaFuncSetAttribute(edge_kernel,
                         cudaFuncAttributeMaxDynamicSharedMemorySize, (int)smem2);

    node_proj_kernel<<<grid1, 256, smem1>>>(node_emb, W1, b1, BN);
    edge_kernel<<<grid2, 256, smem2>>>(edge_index, edge_sel, W1, W2, b2, out,
                                       E, bpb, n_nodes, ntiles);
}

// round 16
// speedup vs baseline: 3.7686x; 1.2346x over previous
#include <cuda_runtime.h>
#include <cuda_fp16.h>
#include <cstdint>
#include <cstddef>

// EdgeEncoder:
//   K1 (proj v2): PERSISTENT, W1a^T/W1b^T in smem once, 64-row tiles,
//       X(t+1) reg-prefetch pipelined; P = f16(X@W1a+b1), Q = f16(X@W1b).
//   K2 (edge, unchanged R14): transposed GEMM2, W2^T static in regs, P/Q cp.async pipelined.
// fp16 mma m16n8k16. edge_index is int32.

#define LDH 136    // fp16 padded row stride (halves)

#define MAXROWS 401408
__device__ half P_buf[(size_t)MAXROWS * 128];
__device__ half Q_buf[(size_t)MAXROWS * 128];

__device__ __forceinline__ uint32_t pack2(float a, float b) {
    half2 h = __floats2half2_rn(a, b);
    return *reinterpret_cast<uint32_t*>(&h);
}
__device__ __forceinline__ float2 unpack2(uint32_t u) {
    return __half22float2(*reinterpret_cast<half2*>(&u));
}
__device__ __forceinline__ uint32_t smem_u32(const void* p) {
    uint32_t a;
    asm("{ .reg .u64 t; cvta.to.shared.u64 t, %1; cvt.u32.u64 %0, t; }" : "=r"(a) : "l"(p));
    return a;
}
__device__ __forceinline__ void cp16(uint32_t dst, const void* src) {
    asm volatile("cp.async.cg.shared.global [%0], [%1], 16;" :: "r"(dst), "l"(src));
}
#define CP_COMMIT() asm volatile("cp.async.commit_group;" ::: "memory")
#define CP_WAIT1()  asm volatile("cp.async.wait_group 1;" ::: "memory")
#define CP_WAIT0()  asm volatile("cp.async.wait_group 0;" ::: "memory")

__device__ __forceinline__ void mma16(float c[4], const uint32_t a[4], uint32_t b0, uint32_t b1) {
    asm("mma.sync.aligned.m16n8k16.row.col.f32.f16.f16.f32 "
        "{%0,%1,%2,%3}, {%4,%5,%6,%7}, {%8,%9}, {%0,%1,%2,%3};"
        : "+f"(c[0]), "+f"(c[1]), "+f"(c[2]), "+f"(c[3])
        : "r"(a[0]), "r"(a[1]), "r"(a[2]), "r"(a[3]), "r"(b0), "r"(b1));
}
__device__ __forceinline__ uint32_t lds32(const half* p) {
    return *reinterpret_cast<const uint32_t*>(p);
}

// W[128k x 128n] fp32 row-major -> WsT[n][k] fp16, LDH stride.
__device__ __forceinline__ void load_wT(half* __restrict__ WsT,
                                        const float* __restrict__ src, int tid) {
    const int n = tid & 127, kh = tid >> 7;
#pragma unroll
    for (int g = 0; g < 8; ++g) {
        const int kb = kh * 64 + g * 8;
        uint4 u;
        u.x = pack2(src[(kb + 0) * 128 + n], src[(kb + 1) * 128 + n]);
        u.y = pack2(src[(kb + 2) * 128 + n], src[(kb + 3) * 128 + n]);
        u.z = pack2(src[(kb + 4) * 128 + n], src[(kb + 5) * 128 + n]);
        u.w = pack2(src[(kb + 6) * 128 + n], src[(kb + 7) * 128 + n]);
        *reinterpret_cast<uint4*>(WsT + n * LDH + kb) = u;
    }
}

// ================= Kernel 1: node projections v2 (persistent, pipelined) ==========
// smem: WsTa 0..34816, WsTb 34816..69632, Xs 69632..87040
#define P_WA 0
#define P_WB 34816
#define P_XS 69632
#define P_SMB 87040

__global__ void __launch_bounds__(256, 2) node_proj_kernel(
    const float* __restrict__ node_emb,
    const float* __restrict__ W1,
    const float* __restrict__ b1,
    int ntiles1)                 // BN/64 (exact)
{
    extern __shared__ char smc[];
    half* WsTa = reinterpret_cast<half*>(smc + P_WA);
    half* WsTb = reinterpret_cast<half*>(smc + P_WB);
    half* Xs   = reinterpret_cast<half*>(smc + P_XS);

    const int tid  = threadIdx.x;
    const int wid  = tid >> 5;
    const int lane = tid & 31;
    const int gq   = lane >> 2;
    const int tq   = lane & 3;
    const int m_warp = (wid & 1) * 32;     // 2 m-splits of 32 rows
    const int n_warp = (wid >> 1) * 32;    // 4 n-splits of 32 cols
    const int xr = tid >> 2;               // node row in tile (0..63)
    const int xq = tid & 3;                // 16B-phase within row

    float b1v[4][2];
#pragma unroll
    for (int nt = 0; nt < 4; ++nt) {
        const int n0 = n_warp + nt * 8 + tq * 2;
        b1v[nt][0] = b1[n0];
        b1v[nt][1] = b1[n0 + 1];
    }

    load_wT(WsTa, W1, tid);
    load_wT(WsTb, W1 + 128 * 128, tid);

    const int stride = gridDim.x;
    const int t0 = blockIdx.x;

    // prefetch X(t0): thread covers cols {xq*4 + i*16 .. +4} (64B-chunk interleave)
    float4 xv[8];
    {
        const float* src = node_emb + (size_t)(t0 * 64 + xr) * 128 + xq * 4;
#pragma unroll
        for (int i = 0; i < 8; ++i)
            xv[i] = *reinterpret_cast<const float4*>(src + i * 16);
    }
    __syncthreads();   // WsTa/WsTb visible

    for (int t = t0; t < ntiles1; t += stride) {
        // convert X(t) regs -> Xs fp16
        {
            half* xrow = Xs + xr * LDH + xq * 4;
#pragma unroll
            for (int i = 0; i < 8; ++i) {
                const float4 v = xv[i];
                *reinterpret_cast<uint2*>(xrow + i * 16) =
                    make_uint2(pack2(v.x, v.y), pack2(v.z, v.w));
            }
        }
        // prefetch X(t+1)
        {
            int t1 = t + stride; if (t1 >= ntiles1) t1 = t;
            const float* src = node_emb + (size_t)(t1 * 64 + xr) * 128 + xq * 4;
#pragma unroll
            for (int i = 0; i < 8; ++i)
                xv[i] = *reinterpret_cast<const float4*>(src + i * 16);
        }
        __syncthreads();   // Xs visible

        const size_t gb = (size_t)t * 64;

        // ---- GEMM P: Xs @ WsTa, then store ----
        float acc[2][4][4];
#pragma unroll
        for (int mt = 0; mt < 2; ++mt)
#pragma unroll
            for (int nt = 0; nt < 4; ++nt)
#pragma unroll
                for (int k = 0; k < 4; ++k) acc[mt][nt][k] = 0.f;

#pragma unroll
        for (int ks = 0; ks < 8; ++ks) {
            const int k0 = ks * 16;
            uint32_t a[2][4];
#pragma unroll
            for (int mt = 0; mt < 2; ++mt) {
                const int r0 = m_warp + mt * 16 + gq;
                a[mt][0] = lds32(Xs + r0 * LDH + k0 + 2 * tq);
                a[mt][1] = lds32(Xs + (r0 + 8) * LDH + k0 + 2 * tq);
                a[mt][2] = lds32(Xs + r0 * LDH + k0 + 8 + 2 * tq);
                a[mt][3] = lds32(Xs + (r0 + 8) * LDH + k0 + 8 + 2 * tq);
            }
#pragma unroll
            for (int nt = 0; nt < 4; ++nt) {
                const int n0 = n_warp + nt * 8 + gq;
                const uint32_t b0 = lds32(WsTa + n0 * LDH + k0 + 2 * tq);
                const uint32_t b1r = lds32(WsTa + n0 * LDH + k0 + 8 + 2 * tq);
                mma16(acc[0][nt], a[0], b0, b1r);
                mma16(acc[1][nt], a[1], b0, b1r);
            }
        }
#pragma unroll
        for (int nt = 0; nt < 4; ++nt) {
            const int n0 = n_warp + nt * 8 + tq * 2;
#pragma unroll
            for (int mt = 0; mt < 2; ++mt) {
                const int r0 = m_warp + mt * 16 + gq;
                *reinterpret_cast<uint32_t*>(P_buf + (gb + r0) * 128 + n0) =
                    pack2(acc[mt][nt][0] + b1v[nt][0], acc[mt][nt][1] + b1v[nt][1]);
                *reinterpret_cast<uint32_t*>(P_buf + (gb + r0 + 8) * 128 + n0) =
                    pack2(acc[mt][nt][2] + b1v[nt][0], acc[mt][nt][3] + b1v[nt][1]);
                acc[mt][nt][0] = acc[mt][nt][1] = acc[mt][nt][2] = acc[mt][nt][3] = 0.f;
            }
        }

        // ---- GEMM Q: Xs @ WsTb, then store ----
#pragma unroll
        for (int ks = 0; ks < 8; ++ks) {
            const int k0 = ks * 16;
            uint32_t a[2][4];
#pragma unroll
            for (int mt = 0; mt < 2; ++mt) {
                const int r0 = m_warp + mt * 16 + gq;
                a[mt][0] = lds32(Xs + r0 * LDH + k0 + 2 * tq);
                a[mt][1] = lds32(Xs + (r0 + 8) * LDH + k0 + 2 * tq);
                a[mt][2] = lds32(Xs + r0 * LDH + k0 + 8 + 2 * tq);
                a[mt][3] = lds32(Xs + (r0 + 8) * LDH + k0 + 8 + 2 * tq);
            }
#pragma unroll
            for (int nt = 0; nt < 4; ++nt) {
                const int n0 = n_warp + nt * 8 + gq;
                const uint32_t b0 = lds32(WsTb + n0 * LDH + k0 + 2 * tq);
                const uint32_t b1r = lds32(WsTb + n0 * LDH + k0 + 8 + 2 * tq);
                mma16(acc[0][nt], a[0], b0, b1r);
                mma16(acc[1][nt], a[1], b0, b1r);
            }
        }
#pragma unroll
        for (int nt = 0; nt < 4; ++nt) {
            const int n0 = n_warp + nt * 8 + tq * 2;
#pragma unroll
            for (int mt = 0; mt < 2; ++mt) {
                const int r0 = m_warp + mt * 16 + gq;
                *reinterpret_cast<uint32_t*>(Q_buf + (gb + r0) * 128 + n0) =
                    pack2(acc[mt][nt][0], acc[mt][nt][1]);
                *reinterpret_cast<uint32_t*>(Q_buf + (gb + r0 + 8) * 128 + n0) =
                    pack2(acc[mt][nt][2], acc[mt][nt][3]);
            }
        }
        __syncthreads();   // Xs reads done before next convert overwrites
    }
}

// ================= Kernel 2: edge (unchanged from R14) =================
#define E_QB   0
#define E_PB   32768
#define E_HB   65536
#define E_SEL  82944
#define E_IDX  83456
#define E_W1C  84480
#define E_SMB  84992

__global__ void __launch_bounds__(256, 2) edge_kernel(
    const int* __restrict__ edge_index,
    const float* __restrict__ edge_sel,
    const float* __restrict__ W1,
    const float* __restrict__ W2,
    const float* __restrict__ b2,
    float* __restrict__ out,
    int E, int bpb, int n_nodes, int ntiles)
{
    extern __shared__ char smc[];
    half*  QB0  = reinterpret_cast<half*>(smc + E_QB);
    half*  PB0  = reinterpret_cast<half*>(smc + E_PB);
    half*  HB   = reinterpret_cast<half*>(smc + E_HB);
    float* sels = reinterpret_cast<float*>(smc + E_SEL);
    int2*  idxs = reinterpret_cast<int2*>(smc + E_IDX);
    float* w1cs = reinterpret_cast<float*>(smc + E_W1C);
    const uint32_t qb_base = smem_u32(smc) + E_QB;
    const uint32_t pb_base = smem_u32(smc) + E_PB;

    const int tid  = threadIdx.x;
    const int wid  = tid >> 5;
    const int lane = tid & 31;
    const int gq   = lane >> 2;
    const int tq   = lane & 3;
    const int oc_warp = (wid & 3) * 32;
    const int e_warp  = (wid >> 2) * 32;
    const int rsub  = lane >> 4;
    const int chunk = lane & 15;

    uint32_t w2a[8][2][4];
#pragma unroll
    for (int ks = 0; ks < 8; ++ks)
#pragma unroll
        for (int mt = 0; mt < 2; ++mt) {
            const int oc = oc_warp + mt * 16 + gq;
            const int k0 = ks * 16 + 2 * tq;
            w2a[ks][mt][0] = pack2(W2[k0 * 128 + oc],       W2[(k0 + 1) * 128 + oc]);
            w2a[ks][mt][1] = pack2(W2[k0 * 128 + oc + 8],   W2[(k0 + 1) * 128 + oc + 8]);
            w2a[ks][mt][2] = pack2(W2[(k0 + 8) * 128 + oc], W2[(k0 + 9) * 128 + oc]);
            w2a[ks][mt][3] = pack2(W2[(k0 + 8) * 128 + oc + 8], W2[(k0 + 9) * 128 + oc + 8]);
        }

    float b2v[2][2];
#pragma unroll
    for (int mt = 0; mt < 2; ++mt) {
        b2v[mt][0] = b2[oc_warp + mt * 16 + gq];
        b2v[mt][1] = b2[oc_warp + mt * 16 + gq + 8];
    }

    const int stride = gridDim.x;
    const int t0 = blockIdx.x;
    auto ebase = [&](int t) -> long long {
        const int b = t / bpb;
        return (long long)b * E + (long long)(t - b * bpb) * 64;
    };

    int2  idx_n;
    float sel_n;
    {
        const long long eb0 = ebase(t0);
        int t1 = t0 + stride; if (t1 >= ntiles) t1 = t0;
        const long long eb1 = ebase(t1);
        if (tid < 64) {
            idxs[tid] = reinterpret_cast<const int2*>(edge_index)[eb0 + tid];
            sels[tid] = edge_sel[eb0 + tid];
            idx_n = reinterpret_cast<const int2*>(edge_index)[eb1 + tid];
            sel_n = edge_sel[eb1 + tid];
        }
        if (tid < 128) w1cs[tid] = W1[256 * 128 + tid];
    }
    __syncthreads();

    {
        const size_t rowbase = (size_t)(t0 / bpb) * n_nodes;
#pragma unroll
        for (int r = 0; r < 4; ++r) {
            const int row = wid * 8 + 2 * r + rsub;
            int iv = idxs[row].y;
            int iu = idxs[row].x;
            iv = min(max(iv, 0), n_nodes - 1);
            iu = min(max(iu, 0), n_nodes - 1);
            cp16(qb_base + (uint32_t)(row * 256 + chunk * 16),
                 Q_buf + (rowbase + iv) * 128 + chunk * 8);
            cp16(pb_base + (uint32_t)(row * 256 + chunk * 16),
                 P_buf + (rowbase + iu) * 128 + chunk * 8);
        }
        CP_COMMIT();
    }

    int i = 0;
    for (int t = t0; t < ntiles; t += stride, ++i) {
        const int cur = i & 1, nxt = cur ^ 1;
        const long long eb = ebase(t);
        int t1 = t + stride; if (t1 >= ntiles) t1 = t;
        const size_t rowbase1 = (size_t)(t1 / bpb) * n_nodes;

        if (tid < 64) {
            idxs[nxt * 64 + tid] = idx_n;
            sels[nxt * 64 + tid] = sel_n;
            int t2 = t + 2 * stride; if (t2 >= ntiles) t2 = t;
            const long long eb2 = ebase(t2);
            idx_n = reinterpret_cast<const int2*>(edge_index)[eb2 + tid];
            sel_n = edge_sel[eb2 + tid];
        }
        __syncthreads();

#pragma unroll
        for (int r = 0; r < 4; ++r) {
            const int row = wid * 8 + 2 * r + rsub;
            int iv = idxs[nxt * 64 + row].y;
            int iu = idxs[nxt * 64 + row].x;
            iv = min(max(iv, 0), n_nodes - 1);
            iu = min(max(iu, 0), n_nodes - 1);
            cp16(qb_base + (uint32_t)(nxt * 16384 + row * 256 + chunk * 16),
                 Q_buf + (rowbase1 + iv) * 128 + chunk * 8);
            cp16(pb_base + (uint32_t)(nxt * 16384 + row * 256 + chunk * 16),
                 P_buf + (rowbase1 + iu) * 128 + chunk * 8);
        }
        CP_COMMIT();

        CP_WAIT1();

        {
            const half* QBc = QB0 + cur * 8192;
            const half* PBc = PB0 + cur * 8192;
            const float4 wa = reinterpret_cast<const float4*>(w1cs + chunk * 8)[0];
            const float4 wb = reinterpret_cast<const float4*>(w1cs + chunk * 8)[1];
#pragma unroll
            for (int r = 0; r < 4; ++r) {
                const int row = wid * 8 + 2 * r + rsub;
                const uint4 q = *reinterpret_cast<const uint4*>(QBc + row * 128 + chunk * 8);
                const uint4 p = *reinterpret_cast<const uint4*>(PBc + row * 128 + chunk * 8);
                const float s = sels[cur * 64 + row];
                const float2 p0 = unpack2(p.x), p1 = unpack2(p.y), p2 = unpack2(p.z), p3 = unpack2(p.w);
                const float2 q0 = unpack2(q.x), q1 = unpack2(q.y), q2 = unpack2(q.z), q3 = unpack2(q.w);
                uint4 h;
                h.x = pack2(fmaxf(p0.x + q0.x + s * wa.x, 0.f),
                            fmaxf(p0.y + q0.y + s * wa.y, 0.f));
                h.y = pack2(fmaxf(p1.x + q1.x + s * wa.z, 0.f),
                            fmaxf(p1.y + q1.y + s * wa.w, 0.f));
                h.z = pack2(fmaxf(p2.x + q2.x + s * wb.x, 0.f),
                            fmaxf(p2.y + q2.y + s * wb.y, 0.f));
                h.w = pack2(fmaxf(p3.x + q3.x + s * wb.z, 0.f),
                            fmaxf(p3.y + q3.y + s * wb.w, 0.f));
                *reinterpret_cast<uint4*>(HB + row * LDH + chunk * 8) = h;
            }
        }
        __syncthreads();

        float acc[2][4][4];
#pragma unroll
        for (int mt = 0; mt < 2; ++mt)
#pragma unroll
            for (int nt = 0; nt < 4; ++nt)
#pragma unroll
                for (int k = 0; k < 4; ++k) acc[mt][nt][k] = 0.f;

#pragma unroll
        for (int ks = 0; ks < 8; ++ks) {
            const int k0 = ks * 16;
#pragma unroll
            for (int nt = 0; nt < 4; ++nt) {
                const int e = e_warp + nt * 8 + gq;
                const uint32_t b0 = lds32(HB + e * LDH + k0 + 2 * tq);
                const uint32_t b1r = lds32(HB + e * LDH + k0 + 8 + 2 * tq);
                mma16(acc[0][nt], w2a[ks][0], b0, b1r);
                mma16(acc[1][nt], w2a[ks][1], b0, b1r);
            }
        }

#pragma unroll
        for (int nt = 0; nt < 4; ++nt) {
            const long long e0 = eb + e_warp + nt * 8 + 2 * tq;
#pragma unroll
            for (int mt = 0; mt < 2; ++mt) {
                const int oc = oc_warp + mt * 16 + gq;
                __stcs(out + (size_t)e0 * 128 + oc,
                       fmaxf(acc[mt][nt][0] + b2v[mt][0], 0.f));
                __stcs(out + (size_t)(e0 + 1) * 128 + oc,
                       fmaxf(acc[mt][nt][1] + b2v[mt][0], 0.f));
                __stcs(out + (size_t)e0 * 128 + oc + 8,
                       fmaxf(acc[mt][nt][2] + b2v[mt][1], 0.f));
                __stcs(out + (size_t)(e0 + 1) * 128 + oc + 8,
                       fmaxf(acc[mt][nt][3] + b2v[mt][1], 0.f));
            }
        }
    }
    CP_WAIT0();
}

extern "C" void kernel_launch(void* const* d_in, const int* in_sizes, int n_in,
                              void* d_out, int out_size) {
    const float* node_emb   = (const float*)d_in[0];
    const int*   edge_index = (const int*)d_in[1];   // int32
    const float* edge_sel   = (const float*)d_in[2];
    const float* W1         = (const float*)d_in[3];
    const float* b1         = (const float*)d_in[4];
    const float* W2         = (const float*)d_in[5];
    const float* b2         = (const float*)d_in[6];
    float*       out        = (float*)d_out;

    const int B  = 4;
    const int E  = in_sizes[2] / B;
    const int n_nodes = in_sizes[0] / (B * 128);
    const int BN = B * n_nodes;

    const int ntiles1 = BN / 64;           // exact for BN=400000
    const int bpb     = E / 64;
    const int ntiles  = B * bpb;

    int dev = 0, sms = 148;
    cudaGetDevice(&dev);
    cudaDeviceGetAttribute(&sms, cudaDevAttrMultiProcessorCount, dev);
    int grid1 = 2 * sms; if (grid1 > ntiles1) grid1 = ntiles1;
    int grid2 = 2 * sms; if (grid2 > ntiles)  grid2 = ntiles;

    cudaFuncSetAttribute(node_proj_kernel,
                         cudaFuncAttributeMaxDynamicSharedMemorySize, P_SMB);
    cudaFuncSetAttribute(edge_kernel,
                         cudaFuncAttributeMaxDynamicSharedMemorySize, E_SMB);

    node_proj_kernel<<<grid1, 256, P_SMB>>>(node_emb, W1, b1, ntiles1);
    edge_kernel<<<grid2, 256, E_SMB>>>(edge_index, edge_sel, W1, W2, b2, out,
                                       E, bpb, n_nodes, ntiles);
}